// round 5
// baseline (speedup 1.0000x reference)
#include <cuda_runtime.h>

// ---------------------------------------------------------------------------
// MultiHeadAttention: out = (ctx @ Wo + bo + q), attn = softmax(QK^T / d_k)
// B=2, L=2048, H=8, d_k=d_v=64, d_model=512
// Round 2: fix __device__ symbol addressing (host shadow-pointer bug);
//          all scratch pointers now resolved via cudaGetSymbolAddress.
// ---------------------------------------------------------------------------

namespace {
constexpr int B  = 2;
constexpr int L  = 2048;
constexpr int NH = 8;
constexpr int DK = 64;
constexpr int DM = 512;
constexpr int HB = NH * B;                       // 16
constexpr long long OUT_ELEMS  = (long long)B * L * DM;   // 2,097,152
constexpr long long ATTN_ELEMS = (long long)HB * L * L;   // 67,108,864
}

// Scratch (allocation-free rule: __device__ globals)
__device__ float g_Qh[HB * L * DK];   // [h*B+b][i][d], pre-scaled by 1/64
__device__ float g_Kh[HB * L * DK];
__device__ float g_Vh[HB * L * DK];
__device__ float g_ctx[HB * L * DK];
__device__ float g_attn_fallback[(size_t)HB * L * L];

// ---------------------------------------------------------------------------
// K1: projection GEMM  out[h*B+b][i][d] = ((A[m] @ W)[n] + bias[n]) * alpha
//     A: [4096, 512] row-major, W: [512, 512] row-major.  64x64 tile, 4x4/thr.
// ---------------------------------------------------------------------------
__global__ void proj_kernel(const float* __restrict__ A,
                            const float* __restrict__ W,
                            const float* __restrict__ bias,
                            float* __restrict__ outp,
                            float alpha) {
    __shared__ float As[32][68];   // [k][m]
    __shared__ float Bs[32][68];   // [k][n]
    const int m0 = blockIdx.y * 64;
    const int n0 = blockIdx.x * 64;
    const int tid = threadIdx.x;
    const int tx = tid & 15, ty = tid >> 4;
    float acc[4][4] = {};
    for (int k0 = 0; k0 < DM; k0 += 32) {
#pragma unroll
        for (int t = 0; t < 8; t++) {
            int idx = tid + t * 256;
            int r = idx >> 5, c = idx & 31;
            As[c][r] = A[(size_t)(m0 + r) * DM + (k0 + c)];
        }
#pragma unroll
        for (int t = 0; t < 8; t++) {
            int idx = tid + t * 256;
            int r = idx >> 6, c = idx & 63;
            Bs[r][c] = W[(size_t)(k0 + r) * DM + (n0 + c)];
        }
        __syncthreads();
#pragma unroll
        for (int kk = 0; kk < 32; kk++) {
            float4 av = *(const float4*)&As[kk][ty * 4];
            float4 bv = *(const float4*)&Bs[kk][tx * 4];
            float a[4] = {av.x, av.y, av.z, av.w};
            float b[4] = {bv.x, bv.y, bv.z, bv.w};
#pragma unroll
            for (int i = 0; i < 4; i++)
#pragma unroll
                for (int j = 0; j < 4; j++)
                    acc[i][j] = fmaf(a[i], b[j], acc[i][j]);
        }
        __syncthreads();
    }
#pragma unroll
    for (int i = 0; i < 4; i++) {
        int m  = m0 + ty * 4 + i;
        int bb = m >> 11;            // m / L
        int ii = m & (L - 1);
#pragma unroll
        for (int j = 0; j < 4; j++) {
            int n = n0 + tx * 4 + j;
            int h = n >> 6, d = n & 63;
            float val = (acc[i][j] + bias[n]) * alpha;
            outp[((size_t)(h * B + bb) * L + ii) * DK + d] = val;
        }
    }
}

// ---------------------------------------------------------------------------
// K2: S = Qh @ Kh^T per (h,b).  128x128 tile, 8x8/thr.  Writes raw scores.
// ---------------------------------------------------------------------------
__global__ void score_kernel(const float* __restrict__ Qh,
                             const float* __restrict__ Kh,
                             float* __restrict__ attn) {
    __shared__ float Qs[32][132];
    __shared__ float Ks[32][132];
    const int hb = blockIdx.z;
    const float* Q = Qh + (size_t)hb * L * DK;
    const float* K = Kh + (size_t)hb * L * DK;
    const int i0 = blockIdx.y * 128;
    const int j0 = blockIdx.x * 128;
    const int tid = threadIdx.x;
    const int tx = tid & 15, ty = tid >> 4;
    float acc[8][8] = {};
    for (int k0 = 0; k0 < DK; k0 += 32) {
#pragma unroll
        for (int t = 0; t < 16; t++) {
            int idx = tid + t * 256;          // 4096 elems each
            int r = idx >> 5, c = idx & 31;
            Qs[c][r] = Q[(size_t)(i0 + r) * DK + k0 + c];
            Ks[c][r] = K[(size_t)(j0 + r) * DK + k0 + c];
        }
        __syncthreads();
#pragma unroll
        for (int kk = 0; kk < 32; kk++) {
            float a[8], b[8];
            *(float4*)&a[0] = *(const float4*)&Qs[kk][ty * 8];
            *(float4*)&a[4] = *(const float4*)&Qs[kk][ty * 8 + 4];
            *(float4*)&b[0] = *(const float4*)&Ks[kk][tx * 8];
            *(float4*)&b[4] = *(const float4*)&Ks[kk][tx * 8 + 4];
#pragma unroll
            for (int i = 0; i < 8; i++)
#pragma unroll
                for (int j = 0; j < 8; j++)
                    acc[i][j] = fmaf(a[i], b[j], acc[i][j]);
        }
        __syncthreads();
    }
    float* outp = attn + (size_t)hb * L * L;
#pragma unroll
    for (int i = 0; i < 8; i++) {
        size_t ro = (size_t)(i0 + ty * 8 + i) * L + (j0 + tx * 8);
        *(float4*)&outp[ro]     = make_float4(acc[i][0], acc[i][1], acc[i][2], acc[i][3]);
        *(float4*)&outp[ro + 4] = make_float4(acc[i][4], acc[i][5], acc[i][6], acc[i][7]);
    }
}

// ---------------------------------------------------------------------------
// K3: in-place masked row softmax over attn.  1 CTA / row, 256 threads.
// ---------------------------------------------------------------------------
__global__ void softmax_kernel(float* __restrict__ attn,
                               const int* __restrict__ mask) {
    const int row = blockIdx.x;               // 0 .. HB*L-1
    const int hb = row >> 11;                 // row / L
    const int i  = row & (L - 1);
    const int bb = hb & (B - 1);              // hb % B  (hb = h*B + b)
    float* p = attn + (size_t)row * L;
    const int* mrow = mask + ((size_t)bb * L + i) * L;
    const int tid = threadIdx.x;

    float vals[8];
    float mx = -3.4e38f;
#pragma unroll
    for (int t = 0; t < 8; t++) {
        int j = tid + t * 256;
        float s = p[j];
        if (mrow[j] == 0) s = -1e9f;
        vals[t] = s;
        mx = fmaxf(mx, s);
    }
    __shared__ float smax[8];
    __shared__ float ssum[8];
#pragma unroll
    for (int off = 16; off; off >>= 1) mx = fmaxf(mx, __shfl_xor_sync(0xffffffffu, mx, off));
    if ((tid & 31) == 0) smax[tid >> 5] = mx;
    __syncthreads();
    mx = smax[0];
#pragma unroll
    for (int w = 1; w < 8; w++) mx = fmaxf(mx, smax[w]);

    float sum = 0.f;
#pragma unroll
    for (int t = 0; t < 8; t++) { vals[t] = __expf(vals[t] - mx); sum += vals[t]; }
#pragma unroll
    for (int off = 16; off; off >>= 1) sum += __shfl_xor_sync(0xffffffffu, sum, off);
    if ((tid & 31) == 0) ssum[tid >> 5] = sum;
    __syncthreads();
    sum = 0.f;
#pragma unroll
    for (int w = 0; w < 8; w++) sum += ssum[w];
    float inv = 1.f / sum;
#pragma unroll
    for (int t = 0; t < 8; t++) p[tid + t * 256] = vals[t] * inv;
}

// ---------------------------------------------------------------------------
// K4: ctx = attn @ Vh per (h,b).  128x64 tile, 8x4/thr, K-loop over L.
// ---------------------------------------------------------------------------
__global__ void ctx_kernel(const float* __restrict__ attn,
                           const float* __restrict__ Vh,
                           float* __restrict__ ctx) {
    __shared__ float Ps[32][132];  // [k][m]
    __shared__ float Vs[32][68];   // [k][n]
    const int hb = blockIdx.y;
    const float* P = attn + (size_t)hb * L * L;
    const float* V = Vh + (size_t)hb * L * DK;
    const int i0 = blockIdx.x * 128;
    const int tid = threadIdx.x;
    const int tx = tid & 15, ty = tid >> 4;
    float acc[8][4] = {};
    for (int k0 = 0; k0 < L; k0 += 32) {
#pragma unroll
        for (int t = 0; t < 16; t++) {
            int idx = tid + t * 256;
            int r = idx >> 5, c = idx & 31;
            Ps[c][r] = P[(size_t)(i0 + r) * L + k0 + c];
        }
#pragma unroll
        for (int t = 0; t < 8; t++) {
            int idx = tid + t * 256;
            int r = idx >> 6, c = idx & 63;
            Vs[r][c] = V[(size_t)(k0 + r) * DK + c];
        }
        __syncthreads();
#pragma unroll
        for (int kk = 0; kk < 32; kk++) {
            float a[8], b[4];
            *(float4*)&a[0] = *(const float4*)&Ps[kk][ty * 8];
            *(float4*)&a[4] = *(const float4*)&Ps[kk][ty * 8 + 4];
            *(float4*)&b[0] = *(const float4*)&Vs[kk][tx * 4];
#pragma unroll
            for (int i = 0; i < 8; i++)
#pragma unroll
                for (int j = 0; j < 4; j++)
                    acc[i][j] = fmaf(a[i], b[j], acc[i][j]);
        }
        __syncthreads();
    }
    float* C = ctx + (size_t)hb * L * DK;
#pragma unroll
    for (int i = 0; i < 8; i++) {
        *(float4*)&C[(size_t)(i0 + ty * 8 + i) * DK + tx * 4] =
            make_float4(acc[i][0], acc[i][1], acc[i][2], acc[i][3]);
    }
}

// ---------------------------------------------------------------------------
// K5: out = gather(ctx) @ Wo + bo + residual(q).  64x64 tile, 4x4/thr.
// ---------------------------------------------------------------------------
__global__ void outproj_kernel(const float* __restrict__ ctx,
                               const float* __restrict__ Wo,
                               const float* __restrict__ bo,
                               const float* __restrict__ resid,
                               float* __restrict__ outp) {
    __shared__ float As[32][68];
    __shared__ float Bs[32][68];
    const int m0 = blockIdx.y * 64;
    const int n0 = blockIdx.x * 64;
    const int tid = threadIdx.x;
    const int tx = tid & 15, ty = tid >> 4;
    float acc[4][4] = {};
    for (int k0 = 0; k0 < DM; k0 += 32) {
#pragma unroll
        for (int t = 0; t < 8; t++) {
            int idx = tid + t * 256;
            int r = idx >> 5, c = idx & 31;
            int m = m0 + r;
            int gc = k0 + c;                 // column h*64+d of gathered ctx
            int h = gc >> 6, d = gc & 63;
            int bb = m >> 11, ii = m & (L - 1);
            As[c][r] = ctx[((size_t)(h * B + bb) * L + ii) * DK + d];
        }
#pragma unroll
        for (int t = 0; t < 8; t++) {
            int idx = tid + t * 256;
            int r = idx >> 6, c = idx & 63;
            Bs[r][c] = Wo[(size_t)(k0 + r) * DM + (n0 + c)];
        }
        __syncthreads();
#pragma unroll
        for (int kk = 0; kk < 32; kk++) {
            float4 av = *(const float4*)&As[kk][ty * 4];
            float4 bv = *(const float4*)&Bs[kk][tx * 4];
            float a[4] = {av.x, av.y, av.z, av.w};
            float b[4] = {bv.x, bv.y, bv.z, bv.w};
#pragma unroll
            for (int i = 0; i < 4; i++)
#pragma unroll
                for (int j = 0; j < 4; j++)
                    acc[i][j] = fmaf(a[i], b[j], acc[i][j]);
        }
        __syncthreads();
    }
#pragma unroll
    for (int i = 0; i < 4; i++) {
        int m = m0 + ty * 4 + i;
#pragma unroll
        for (int j = 0; j < 4; j++) {
            int n = n0 + tx * 4 + j;
            outp[(size_t)m * DM + n] = acc[i][j] + bo[n] + resid[(size_t)m * DM + n];
        }
    }
}

// ---------------------------------------------------------------------------
extern "C" void kernel_launch(void* const* d_in, const int* in_sizes, int n_in,
                              void* d_out, int out_size) {
    const float* q    = (const float*)d_in[0];
    const float* k    = (const float*)d_in[1];
    const float* v    = (const float*)d_in[2];
    const int*   mask = (const int*)  d_in[3];
    const float* Wq   = (const float*)d_in[4];
    const float* bq   = (const float*)d_in[5];
    const float* Wk   = (const float*)d_in[6];
    const float* bk   = (const float*)d_in[7];
    const float* Wv   = (const float*)d_in[8];
    const float* bv   = (const float*)d_in[9];
    const float* Wo   = (const float*)d_in[10];
    const float* bo   = (const float*)d_in[11];
    float* outp = (float*)d_out;

    // Resolve REAL device addresses of the __device__ scratch symbols.
    // (Passing the symbol name from host code passes the host shadow -> R1 bug.)
    float *Qh, *Kh, *Vh, *Ctx, *AttnFB;
    cudaGetSymbolAddress((void**)&Qh,     g_Qh);
    cudaGetSymbolAddress((void**)&Kh,     g_Kh);
    cudaGetSymbolAddress((void**)&Vh,     g_Vh);
    cudaGetSymbolAddress((void**)&Ctx,    g_ctx);
    cudaGetSymbolAddress((void**)&AttnFB, g_attn_fallback);

    // attn region of d_out if present (reference returns (out, attn) concatenated)
    float* attn = ((long long)out_size >= OUT_ELEMS + ATTN_ELEMS)
                      ? (outp + OUT_ELEMS) : AttnFB;

    const dim3 blk(256);
    const float inv_dk = 1.0f / (float)DK;   // reference uses temperature = d_k

    // 1) projections: [4096,512] @ [512,512], scatter to [h*B+b][i][d]
    proj_kernel<<<dim3(DM / 64, (B * L) / 64), blk>>>(q, Wq, bq, Qh, inv_dk);
    proj_kernel<<<dim3(DM / 64, (B * L) / 64), blk>>>(k, Wk, bk, Kh, 1.0f);
    proj_kernel<<<dim3(DM / 64, (B * L) / 64), blk>>>(v, Wv, bv, Vh, 1.0f);

    // 2) raw scores
    score_kernel<<<dim3(L / 128, L / 128, HB), blk>>>(Qh, Kh, attn);

    // 3) masked softmax (in place)
    softmax_kernel<<<dim3(HB * L), blk>>>(attn, mask);

    // 4) ctx = attn @ V
    ctx_kernel<<<dim3(L / 128, HB), blk>>>(attn, Vh, Ctx);

    // 5) output projection + bias + residual
    outproj_kernel<<<dim3(DM / 64, (B * L) / 64), blk>>>(Ctx, Wo, bo, q, outp);
}

// round 7
// speedup vs baseline: 1.0791x; 1.0791x over previous
#include <cuda_runtime.h>
#include <cstdint>

// ---------------------------------------------------------------------------
// MultiHeadAttention, B=2, L=2048, H=8, d=64, d_model=512
// Round 6: fix P-tile smem overflow (Ps was 128x68 but P is 128x128; rows
//          aliased and row 127 overflowed into the K tile). P now 128x132.
// ---------------------------------------------------------------------------

namespace {
constexpr int B  = 2;
constexpr int L  = 2048;
constexpr int DK = 64;
constexpr int DM = 512;
constexpr int HB = 16;                                    // NH * B
constexpr long long OUT_ELEMS  = (long long)B * L * DM;
constexpr long long ATTN_ELEMS = (long long)HB * L * L;

// fused-kernel smem layout (float offsets)
constexpr int PSTR    = 132;      // P tile stride (128 cols + pad)
constexpr int PS_OFF  = 0;        // P / Q-staging: 128 x 132 = 16896
constexpr int KS_OFF0 = 16896;    // K tile: 128 x 68
constexpr int KS_OFF1 = 25600;
constexpr int VS_OFF0 = 34304;    // V tile: 128 x 72
constexpr int VS_OFF1 = 43520;
constexpr int MB_OFF  = 52736;    // 512 uint32 mask bits
constexpr int RS_OFF  = 53248;    // rowsum[128]
constexpr int INV_OFF = 53376;    // inv[128]
constexpr int SMEM_FLOATS = 53504;
constexpr int SMEM_BYTES  = SMEM_FLOATS * 4;   // 214016 < 227KB cap
}

// Scratch (__device__ globals; addresses resolved via cudaGetSymbolAddress)
__device__ float g_Qh[HB * L * DK];   // tf32-rounded, pre-scaled by 1/64
__device__ float g_Kh[HB * L * DK];   // tf32-rounded
__device__ float g_Vh[HB * L * DK];   // tf32-rounded
__device__ float g_ctx[HB * L * DK];
__device__ float g_attn_fallback[(size_t)HB * L * L];

// ---------------------------------------------------------------------------
__device__ __forceinline__ uint32_t f2tf32(float f) {
    uint32_t u;
    asm("cvt.rna.tf32.f32 %0, %1;" : "=r"(u) : "f"(f));
    return u;
}
__device__ __forceinline__ void mma_tf32(float* c, const uint32_t* a, const uint32_t* b) {
    asm volatile(
        "mma.sync.aligned.m16n8k8.row.col.f32.tf32.tf32.f32 "
        "{%0,%1,%2,%3},{%4,%5,%6,%7},{%8,%9},{%0,%1,%2,%3};"
        : "+f"(c[0]), "+f"(c[1]), "+f"(c[2]), "+f"(c[3])
        : "r"(a[0]), "r"(a[1]), "r"(a[2]), "r"(a[3]), "r"(b[0]), "r"(b[1]));
}
__device__ __forceinline__ void cp_async16(void* sdst, const void* gsrc) {
    uint32_t da = (uint32_t)__cvta_generic_to_shared(sdst);
    asm volatile("cp.async.cg.shared.global [%0], [%1], 16;" :: "r"(da), "l"(gsrc));
}
__device__ __forceinline__ void cp_commit() { asm volatile("cp.async.commit_group;"); }
__device__ __forceinline__ void cp_wait_all() { asm volatile("cp.async.wait_group 0;"); }
__device__ __forceinline__ uint32_t asu(float f) { return __float_as_uint(f); }

// ---------------------------------------------------------------------------
// K1: projection GEMM. out[h*B+b][i][d] = tf32(((A@W)[n] + bias[n]) * alpha)
// ---------------------------------------------------------------------------
__global__ void proj_kernel(const float* __restrict__ A,
                            const float* __restrict__ W,
                            const float* __restrict__ bias,
                            float* __restrict__ outp,
                            float alpha) {
    __shared__ float As[32][68];
    __shared__ float Bs[32][68];
    const int m0 = blockIdx.y * 64;
    const int n0 = blockIdx.x * 64;
    const int tid = threadIdx.x;
    const int tx = tid & 15, ty = tid >> 4;
    float acc[4][4] = {};
    for (int k0 = 0; k0 < DM; k0 += 32) {
#pragma unroll
        for (int t = 0; t < 8; t++) {
            int idx = tid + t * 256;
            int r = idx >> 5, c = idx & 31;
            As[c][r] = A[(size_t)(m0 + r) * DM + (k0 + c)];
        }
#pragma unroll
        for (int t = 0; t < 8; t++) {
            int idx = tid + t * 256;
            int r = idx >> 6, c = idx & 63;
            Bs[r][c] = W[(size_t)(k0 + r) * DM + (n0 + c)];
        }
        __syncthreads();
#pragma unroll
        for (int kk = 0; kk < 32; kk++) {
            float4 av = *(const float4*)&As[kk][ty * 4];
            float4 bv = *(const float4*)&Bs[kk][tx * 4];
            float a[4] = {av.x, av.y, av.z, av.w};
            float b[4] = {bv.x, bv.y, bv.z, bv.w};
#pragma unroll
            for (int i = 0; i < 4; i++)
#pragma unroll
                for (int j = 0; j < 4; j++)
                    acc[i][j] = fmaf(a[i], b[j], acc[i][j]);
        }
        __syncthreads();
    }
#pragma unroll
    for (int i = 0; i < 4; i++) {
        int m  = m0 + ty * 4 + i;
        int bb = m >> 11, ii = m & (L - 1);
#pragma unroll
        for (int j = 0; j < 4; j++) {
            int n = n0 + tx * 4 + j;
            int h = n >> 6, d = n & 63;
            float val = (acc[i][j] + bias[n]) * alpha;
            outp[((size_t)(h * B + bb) * L + ii) * DK + d] = __uint_as_float(f2tf32(val));
        }
    }
}

// ---------------------------------------------------------------------------
// K2: fused attention.  grid (16 iblocks, 16 hb), 256 threads, 1 CTA/SM.
// ---------------------------------------------------------------------------
__global__ __launch_bounds__(256, 1)
void fused_attn_kernel(const float* __restrict__ Qh,
                       const float* __restrict__ Kh,
                       const float* __restrict__ Vh,
                       const int*   __restrict__ mask,
                       float* __restrict__ attn,
                       float* __restrict__ ctx) {
    extern __shared__ float sm[];
    float* Ps = sm + PS_OFF;                  // 128 x PSTR
    uint32_t* mbits = (uint32_t*)(sm + MB_OFF);
    float* rowsum_s = sm + RS_OFF;
    float* inv_s    = sm + INV_OFF;

    const int i0 = blockIdx.x * 128;
    const int hb = blockIdx.y;
    const int bb = hb & (B - 1);
    const int tid = threadIdx.x;
    const int wid = tid >> 5, lane = tid & 31;
    const int g = lane >> 2, tp = lane & 3;
    const int wm0  = (wid >> 1) * 32;       // M range of this warp
    const int wn0  = (wid & 1) * 64;        // N range for S (64 wide)
    const int wn0p = (wid & 1) * 32;        // N range for PV (32 wide)

    const float* Qb = Qh + (size_t)hb * L * DK;
    const float* Kb = Kh + (size_t)hb * L * DK;
    const float* Vb = Vh + (size_t)hb * L * DK;
    float* attnb = attn + (size_t)hb * L * L;

    if (tid < 128) rowsum_s[tid] = 0.f;

    // ---- stage Q into Ps, extract A-fragments to registers ----
    for (int t = tid; t < 2048; t += 256) {            // 128 rows x 16 float4
        int r = t >> 4, c4 = t & 15;
        *(float4*)&Ps[r * PSTR + c4 * 4] =
            *(const float4*)&Qb[(size_t)(i0 + r) * DK + c4 * 4];
    }
    __syncthreads();
    uint32_t qf[2][8][4];
#pragma unroll
    for (int mi = 0; mi < 2; mi++) {
        int r = wm0 + mi * 16 + g;
#pragma unroll
        for (int ks = 0; ks < 8; ks++) {
            qf[mi][ks][0] = asu(Ps[r * PSTR + ks * 8 + tp]);
            qf[mi][ks][1] = asu(Ps[(r + 8) * PSTR + ks * 8 + tp]);
            qf[mi][ks][2] = asu(Ps[r * PSTR + ks * 8 + tp + 4]);
            qf[mi][ks][3] = asu(Ps[(r + 8) * PSTR + ks * 8 + tp + 4]);
        }
    }
    __syncthreads();   // Ps now free for P tiles

    // ---- K/V tile loader (cp.async, double-buffered) ----
    auto load_kv = [&](int jt, int buf) {
        const int j0 = jt * 128;
        float* Kd = sm + (buf ? KS_OFF1 : KS_OFF0);
        float* Vd = sm + (buf ? VS_OFF1 : VS_OFF0);
        for (int t = tid; t < 2048; t += 256) {
            int r = t >> 4, c4 = t & 15;
            cp_async16(&Kd[r * 68 + c4 * 4], &Kb[(size_t)(j0 + r) * DK + c4 * 4]);
            cp_async16(&Vd[r * 72 + c4 * 4], &Vb[(size_t)(j0 + r) * DK + c4 * 4]);
        }
    };
    load_kv(0, 0);
    cp_commit();

    float cv[2][4][4] = {};       // PV accumulator (persistent)
    float rsum[4] = {0.f, 0.f, 0.f, 0.f};

    for (int jt = 0; jt < 16; jt++) {
        const int cur = jt & 1;
        const int j0 = jt * 128;
        cp_wait_all();
        __syncthreads();                       // K/V[cur] ready; prev PV done with Ps
        if (jt + 1 < 16) { load_kv(jt + 1, cur ^ 1); cp_commit(); }

        // ---- pack mask tile into bits (512 words), per-warp 64 words ----
        for (int t0 = 0; t0 < 64; t0 += 8) {
            int mv[8];
#pragma unroll
            for (int u = 0; u < 8; u++) {
                int w = wid * 64 + t0 + u;
                int r = w >> 2, c32 = w & 3;
                mv[u] = mask[((size_t)bb * L + i0 + r) * L + j0 + c32 * 32 + lane];
            }
#pragma unroll
            for (int u = 0; u < 8; u++) {
                unsigned bal = __ballot_sync(0xffffffffu, mv[u] != 0);
                if (lane == 0) mbits[wid * 64 + t0 + u] = bal;
            }
        }

        // ---- S = Q @ K^T ----
        float sacc[2][8][4] = {};
        const float* Kt = sm + (cur ? KS_OFF1 : KS_OFF0);
#pragma unroll
        for (int ks = 0; ks < 8; ks++) {
            uint32_t bf[8][2];
#pragma unroll
            for (int ni = 0; ni < 8; ni++) {
                bf[ni][0] = asu(Kt[(wn0 + ni * 8 + g) * 68 + ks * 8 + tp]);
                bf[ni][1] = asu(Kt[(wn0 + ni * 8 + g) * 68 + ks * 8 + tp + 4]);
            }
#pragma unroll
            for (int mi = 0; mi < 2; mi++)
#pragma unroll
                for (int ni = 0; ni < 8; ni++)
                    mma_tf32(sacc[mi][ni], qf[mi][ks], bf[ni]);
        }
        __syncthreads();                       // mbits visible; Ps free

        // ---- E = mask ? exp(S) : 0 ; tf32-round; store to Ps; rowsum ----
#pragma unroll
        for (int mi = 0; mi < 2; mi++) {
            int r0 = wm0 + mi * 16 + g;
            int r1 = r0 + 8;
            uint32_t w0a = mbits[r0 * 4 + (wn0 >> 5)];
            uint32_t w0b = mbits[r0 * 4 + (wn0 >> 5) + 1];
            uint32_t w1a = mbits[r1 * 4 + (wn0 >> 5)];
            uint32_t w1b = mbits[r1 * 4 + (wn0 >> 5) + 1];
#pragma unroll
            for (int ni = 0; ni < 8; ni++) {
                int c = wn0 + ni * 8 + tp * 2;
                uint32_t w0 = (ni < 4) ? w0a : w0b;
                uint32_t w1 = (ni < 4) ? w1a : w1b;
                int sh = c & 31;
                float e00 = ((w0 >> sh) & 1u)       ? __expf(sacc[mi][ni][0]) : 0.f;
                float e01 = ((w0 >> (sh + 1)) & 1u) ? __expf(sacc[mi][ni][1]) : 0.f;
                float e10 = ((w1 >> sh) & 1u)       ? __expf(sacc[mi][ni][2]) : 0.f;
                float e11 = ((w1 >> (sh + 1)) & 1u) ? __expf(sacc[mi][ni][3]) : 0.f;
                e00 = __uint_as_float(f2tf32(e00));
                e01 = __uint_as_float(f2tf32(e01));
                e10 = __uint_as_float(f2tf32(e10));
                e11 = __uint_as_float(f2tf32(e11));
                rsum[mi * 2]     += e00 + e01;
                rsum[mi * 2 + 1] += e10 + e11;
                *(float2*)&Ps[r0 * PSTR + c] = make_float2(e00, e01);
                *(float2*)&Ps[r1 * PSTR + c] = make_float2(e10, e11);
            }
        }
        __syncthreads();                       // full P tile ready

        // ---- coalesced copy P -> gmem attn (unnormalized) ----
        for (int t = tid; t < 4096; t += 256) {        // 128 rows x 32 float4
            int r = t >> 5, c4 = t & 31;
            *(float4*)&attnb[(size_t)(i0 + r) * L + j0 + c4 * 4] =
                *(float4*)&Ps[r * PSTR + c4 * 4];
        }

        // ---- ctx += P @ V ----
        const float* Vt = sm + (cur ? VS_OFF1 : VS_OFF0);
#pragma unroll
        for (int kp = 0; kp < 16; kp++) {
            uint32_t af[2][4], bf2[4][2];
#pragma unroll
            for (int mi = 0; mi < 2; mi++) {
                int r = wm0 + mi * 16 + g;
                af[mi][0] = asu(Ps[r * PSTR + kp * 8 + tp]);
                af[mi][1] = asu(Ps[(r + 8) * PSTR + kp * 8 + tp]);
                af[mi][2] = asu(Ps[r * PSTR + kp * 8 + tp + 4]);
                af[mi][3] = asu(Ps[(r + 8) * PSTR + kp * 8 + tp + 4]);
            }
#pragma unroll
            for (int ni = 0; ni < 4; ni++) {
                bf2[ni][0] = asu(Vt[(kp * 8 + tp) * 72 + wn0p + ni * 8 + g]);
                bf2[ni][1] = asu(Vt[(kp * 8 + tp + 4) * 72 + wn0p + ni * 8 + g]);
            }
#pragma unroll
            for (int mi = 0; mi < 2; mi++)
#pragma unroll
                for (int ni = 0; ni < 4; ni++)
                    mma_tf32(cv[mi][ni], af[mi], bf2[ni]);
        }
    }

    // ---- rowsum reduction ----
#pragma unroll
    for (int s = 0; s < 4; s++) {
        rsum[s] += __shfl_xor_sync(0xffffffffu, rsum[s], 1);
        rsum[s] += __shfl_xor_sync(0xffffffffu, rsum[s], 2);
    }
    if (tp == 0) {
#pragma unroll
        for (int mi = 0; mi < 2; mi++) {
            atomicAdd(&rowsum_s[wm0 + mi * 16 + g],     rsum[mi * 2]);
            atomicAdd(&rowsum_s[wm0 + mi * 16 + g + 8], rsum[mi * 2 + 1]);
        }
    }
    __syncthreads();
    if (tid < 128) inv_s[tid] = 1.0f / rowsum_s[tid];
    __syncthreads();

    // ---- write ctx (normalized) ----
    float* ctxb = ctx + (size_t)hb * L * DK;
#pragma unroll
    for (int mi = 0; mi < 2; mi++) {
        int r0 = wm0 + mi * 16 + g;
        float iv0 = inv_s[r0], iv1 = inv_s[r0 + 8];
#pragma unroll
        for (int ni = 0; ni < 4; ni++) {
            int c = wn0p + ni * 8 + tp * 2;
            *(float2*)&ctxb[(size_t)(i0 + r0) * DK + c] =
                make_float2(cv[mi][ni][0] * iv0, cv[mi][ni][1] * iv0);
            *(float2*)&ctxb[(size_t)(i0 + r0 + 8) * DK + c] =
                make_float2(cv[mi][ni][2] * iv1, cv[mi][ni][3] * iv1);
        }
    }

    // ---- rescale attn block in gmem (L2-warm) ----
    for (int t = tid; t < 128 * 512; t += 256) {       // 128 rows x 512 float4
        int r = t >> 9, c4 = t & 511;
        float iv = inv_s[r];
        float4 v = *(float4*)&attnb[(size_t)(i0 + r) * L + c4 * 4];
        v.x *= iv; v.y *= iv; v.z *= iv; v.w *= iv;
        *(float4*)&attnb[(size_t)(i0 + r) * L + c4 * 4] = v;
    }
}

// ---------------------------------------------------------------------------
// K3: out = gather(ctx) @ Wo + bo + residual(q).  64x64 tile, 4x4/thr.
// ---------------------------------------------------------------------------
__global__ void outproj_kernel(const float* __restrict__ ctx,
                               const float* __restrict__ Wo,
                               const float* __restrict__ bo,
                               const float* __restrict__ resid,
                               float* __restrict__ outp) {
    __shared__ float As[32][68];
    __shared__ float Bs[32][68];
    const int m0 = blockIdx.y * 64;
    const int n0 = blockIdx.x * 64;
    const int tid = threadIdx.x;
    const int tx = tid & 15, ty = tid >> 4;
    float acc[4][4] = {};
    for (int k0 = 0; k0 < DM; k0 += 32) {
#pragma unroll
        for (int t = 0; t < 8; t++) {
            int idx = tid + t * 256;
            int r = idx >> 5, c = idx & 31;
            int m = m0 + r;
            int gc = k0 + c;
            int h = gc >> 6, d = gc & 63;
            int bb = m >> 11, ii = m & (L - 1);
            As[c][r] = ctx[((size_t)(h * B + bb) * L + ii) * DK + d];
        }
#pragma unroll
        for (int t = 0; t < 8; t++) {
            int idx = tid + t * 256;
            int r = idx >> 6, c = idx & 63;
            Bs[r][c] = Wo[(size_t)(k0 + r) * DM + (n0 + c)];
        }
        __syncthreads();
#pragma unroll
        for (int kk = 0; kk < 32; kk++) {
            float4 av = *(const float4*)&As[kk][ty * 4];
            float4 bv = *(const float4*)&Bs[kk][tx * 4];
            float a[4] = {av.x, av.y, av.z, av.w};
            float b[4] = {bv.x, bv.y, bv.z, bv.w};
#pragma unroll
            for (int i = 0; i < 4; i++)
#pragma unroll
                for (int j = 0; j < 4; j++)
                    acc[i][j] = fmaf(a[i], b[j], acc[i][j]);
        }
        __syncthreads();
    }
#pragma unroll
    for (int i = 0; i < 4; i++) {
        int m = m0 + ty * 4 + i;
#pragma unroll
        for (int j = 0; j < 4; j++) {
            int n = n0 + tx * 4 + j;
            outp[(size_t)m * DM + n] = acc[i][j] + bo[n] + resid[(size_t)m * DM + n];
        }
    }
}

// ---------------------------------------------------------------------------
extern "C" void kernel_launch(void* const* d_in, const int* in_sizes, int n_in,
                              void* d_out, int out_size) {
    const float* q    = (const float*)d_in[0];
    const float* k    = (const float*)d_in[1];
    const float* v    = (const float*)d_in[2];
    const int*   mask = (const int*)  d_in[3];
    const float* Wq   = (const float*)d_in[4];
    const float* bq   = (const float*)d_in[5];
    const float* Wk   = (const float*)d_in[6];
    const float* bk   = (const float*)d_in[7];
    const float* Wv   = (const float*)d_in[8];
    const float* bv   = (const float*)d_in[9];
    const float* Wo   = (const float*)d_in[10];
    const float* bo   = (const float*)d_in[11];
    float* outp = (float*)d_out;

    float *Qh, *Kh, *Vh, *Ctx, *AttnFB;
    cudaGetSymbolAddress((void**)&Qh,     g_Qh);
    cudaGetSymbolAddress((void**)&Kh,     g_Kh);
    cudaGetSymbolAddress((void**)&Vh,     g_Vh);
    cudaGetSymbolAddress((void**)&Ctx,    g_ctx);
    cudaGetSymbolAddress((void**)&AttnFB, g_attn_fallback);

    float* attn = ((long long)out_size >= OUT_ELEMS + ATTN_ELEMS)
                      ? (outp + OUT_ELEMS) : AttnFB;

    cudaFuncSetAttribute(fused_attn_kernel,
                         cudaFuncAttributeMaxDynamicSharedMemorySize, SMEM_BYTES);

    const dim3 blk(256);
    const float inv_dk = 1.0f / 64.0f;     // temperature = d_k

    proj_kernel<<<dim3(DM / 64, (B * L) / 64), blk>>>(q, Wq, bq, Qh, inv_dk);
    proj_kernel<<<dim3(DM / 64, (B * L) / 64), blk>>>(k, Wk, bk, Kh, 1.0f);
    proj_kernel<<<dim3(DM / 64, (B * L) / 64), blk>>>(v, Wv, bv, Vh, 1.0f);

    fused_attn_kernel<<<dim3(L / 128, HB), blk, SMEM_BYTES>>>(Qh, Kh, Vh, mask, attn, Ctx);

    outproj_kernel<<<dim3(DM / 64, (B * L) / 64), blk>>>(Ctx, Wo, bo, q, outp);
}

// round 8
// speedup vs baseline: 1.3135x; 1.2173x over previous
#include <cuda_runtime.h>
#include <cstdint>

// ---------------------------------------------------------------------------
// MultiHeadAttention, B=2, L=2048, H=8, d=64, d_model=512
// Round 7: fused attention restructured 8 warps -> 16 warps (512 thr), M=16
//          per warp. Halves per-thread registers (was 255 w/ spills), doubles
//          latency hiding. Tile/smem layout unchanged.
// ---------------------------------------------------------------------------

namespace {
constexpr int B  = 2;
constexpr int L  = 2048;
constexpr int DK = 64;
constexpr int DM = 512;
constexpr int HB = 16;                                    // NH * B
constexpr long long OUT_ELEMS  = (long long)B * L * DM;
constexpr long long ATTN_ELEMS = (long long)HB * L * L;

// fused-kernel smem layout (float offsets)
constexpr int PSTR    = 132;      // P tile stride (128 cols + pad)
constexpr int PS_OFF  = 0;        // P / Q-staging: 128 x 132 = 16896
constexpr int KS_OFF0 = 16896;    // K tile: 128 x 68
constexpr int KS_OFF1 = 25600;
constexpr int VS_OFF0 = 34304;    // V tile: 128 x 72
constexpr int VS_OFF1 = 43520;
constexpr int MB_OFF  = 52736;    // 512 uint32 mask bits
constexpr int RS_OFF  = 53248;    // rowsum[128]
constexpr int INV_OFF = 53376;    // inv[128]
constexpr int SMEM_FLOATS = 53504;
constexpr int SMEM_BYTES  = SMEM_FLOATS * 4;   // 214016 < 227KB cap
}

// Scratch (__device__ globals; addresses resolved via cudaGetSymbolAddress)
__device__ float g_Qh[HB * L * DK];   // tf32-rounded, pre-scaled by 1/64
__device__ float g_Kh[HB * L * DK];   // tf32-rounded
__device__ float g_Vh[HB * L * DK];   // tf32-rounded
__device__ float g_ctx[HB * L * DK];
__device__ float g_attn_fallback[(size_t)HB * L * L];

// ---------------------------------------------------------------------------
__device__ __forceinline__ uint32_t f2tf32(float f) {
    uint32_t u;
    asm("cvt.rna.tf32.f32 %0, %1;" : "=r"(u) : "f"(f));
    return u;
}
__device__ __forceinline__ void mma_tf32(float* c, const uint32_t* a, const uint32_t* b) {
    asm volatile(
        "mma.sync.aligned.m16n8k8.row.col.f32.tf32.tf32.f32 "
        "{%0,%1,%2,%3},{%4,%5,%6,%7},{%8,%9},{%0,%1,%2,%3};"
        : "+f"(c[0]), "+f"(c[1]), "+f"(c[2]), "+f"(c[3])
        : "r"(a[0]), "r"(a[1]), "r"(a[2]), "r"(a[3]), "r"(b[0]), "r"(b[1]));
}
__device__ __forceinline__ void cp_async16(void* sdst, const void* gsrc) {
    uint32_t da = (uint32_t)__cvta_generic_to_shared(sdst);
    asm volatile("cp.async.cg.shared.global [%0], [%1], 16;" :: "r"(da), "l"(gsrc));
}
__device__ __forceinline__ void cp_commit() { asm volatile("cp.async.commit_group;"); }
__device__ __forceinline__ void cp_wait_all() { asm volatile("cp.async.wait_group 0;"); }
__device__ __forceinline__ uint32_t asu(float f) { return __float_as_uint(f); }

// ---------------------------------------------------------------------------
// K1: projection GEMM. out[h*B+b][i][d] = tf32(((A@W)[n] + bias[n]) * alpha)
// ---------------------------------------------------------------------------
__global__ void proj_kernel(const float* __restrict__ A,
                            const float* __restrict__ W,
                            const float* __restrict__ bias,
                            float* __restrict__ outp,
                            float alpha) {
    __shared__ float As[32][68];
    __shared__ float Bs[32][68];
    const int m0 = blockIdx.y * 64;
    const int n0 = blockIdx.x * 64;
    const int tid = threadIdx.x;
    const int tx = tid & 15, ty = tid >> 4;
    float acc[4][4] = {};
    for (int k0 = 0; k0 < DM; k0 += 32) {
#pragma unroll
        for (int t = 0; t < 8; t++) {
            int idx = tid + t * 256;
            int r = idx >> 5, c = idx & 31;
            As[c][r] = A[(size_t)(m0 + r) * DM + (k0 + c)];
        }
#pragma unroll
        for (int t = 0; t < 8; t++) {
            int idx = tid + t * 256;
            int r = idx >> 6, c = idx & 63;
            Bs[r][c] = W[(size_t)(k0 + r) * DM + (n0 + c)];
        }
        __syncthreads();
#pragma unroll
        for (int kk = 0; kk < 32; kk++) {
            float4 av = *(const float4*)&As[kk][ty * 4];
            float4 bv = *(const float4*)&Bs[kk][tx * 4];
            float a[4] = {av.x, av.y, av.z, av.w};
            float b[4] = {bv.x, bv.y, bv.z, bv.w};
#pragma unroll
            for (int i = 0; i < 4; i++)
#pragma unroll
                for (int j = 0; j < 4; j++)
                    acc[i][j] = fmaf(a[i], b[j], acc[i][j]);
        }
        __syncthreads();
    }
#pragma unroll
    for (int i = 0; i < 4; i++) {
        int m  = m0 + ty * 4 + i;
        int bb = m >> 11, ii = m & (L - 1);
#pragma unroll
        for (int j = 0; j < 4; j++) {
            int n = n0 + tx * 4 + j;
            int h = n >> 6, d = n & 63;
            float val = (acc[i][j] + bias[n]) * alpha;
            outp[((size_t)(h * B + bb) * L + ii) * DK + d] = __uint_as_float(f2tf32(val));
        }
    }
}

// ---------------------------------------------------------------------------
// K2: fused attention.  grid (16 iblocks, 16 hb), 512 threads, 1 CTA/SM.
//   16 warps: warp grid 8(M=16 rows) x 2(N=64 cols for S / 32 for PV).
// ---------------------------------------------------------------------------
__global__ __launch_bounds__(512, 1)
void fused_attn_kernel(const float* __restrict__ Qh,
                       const float* __restrict__ Kh,
                       const float* __restrict__ Vh,
                       const int*   __restrict__ mask,
                       float* __restrict__ attn,
                       float* __restrict__ ctx) {
    extern __shared__ float sm[];
    float* Ps = sm + PS_OFF;                  // 128 x PSTR
    uint32_t* mbits = (uint32_t*)(sm + MB_OFF);
    float* rowsum_s = sm + RS_OFF;
    float* inv_s    = sm + INV_OFF;

    const int i0 = blockIdx.x * 128;
    const int hb = blockIdx.y;
    const int bb = hb & (B - 1);
    const int tid = threadIdx.x;
    const int wid = tid >> 5, lane = tid & 31;
    const int g = lane >> 2, tp = lane & 3;
    const int wm0  = (wid >> 1) * 16;       // 16 M-rows per warp
    const int wn0  = (wid & 1) * 64;        // N range for S (64 wide)
    const int wn0p = (wid & 1) * 32;        // N range for PV (32 wide)

    const float* Qb = Qh + (size_t)hb * L * DK;
    const float* Kb = Kh + (size_t)hb * L * DK;
    const float* Vb = Vh + (size_t)hb * L * DK;
    float* attnb = attn + (size_t)hb * L * L;

    if (tid < 128) rowsum_s[tid] = 0.f;

    // ---- stage Q into Ps, extract A-fragments to registers ----
    for (int t = tid; t < 2048; t += 512) {            // 128 rows x 16 float4
        int r = t >> 4, c4 = t & 15;
        *(float4*)&Ps[r * PSTR + c4 * 4] =
            *(const float4*)&Qb[(size_t)(i0 + r) * DK + c4 * 4];
    }
    __syncthreads();
    uint32_t qf[8][4];
    {
        int r = wm0 + g;
#pragma unroll
        for (int ks = 0; ks < 8; ks++) {
            qf[ks][0] = asu(Ps[r * PSTR + ks * 8 + tp]);
            qf[ks][1] = asu(Ps[(r + 8) * PSTR + ks * 8 + tp]);
            qf[ks][2] = asu(Ps[r * PSTR + ks * 8 + tp + 4]);
            qf[ks][3] = asu(Ps[(r + 8) * PSTR + ks * 8 + tp + 4]);
        }
    }
    __syncthreads();   // Ps now free for P tiles

    // ---- K/V tile loader (cp.async, double-buffered) ----
    auto load_kv = [&](int jt, int buf) {
        const int j0 = jt * 128;
        float* Kd = sm + (buf ? KS_OFF1 : KS_OFF0);
        float* Vd = sm + (buf ? VS_OFF1 : VS_OFF0);
        for (int t = tid; t < 2048; t += 512) {
            int r = t >> 4, c4 = t & 15;
            cp_async16(&Kd[r * 68 + c4 * 4], &Kb[(size_t)(j0 + r) * DK + c4 * 4]);
            cp_async16(&Vd[r * 72 + c4 * 4], &Vb[(size_t)(j0 + r) * DK + c4 * 4]);
        }
    };
    load_kv(0, 0);
    cp_commit();

    float cv[4][4] = {};          // PV accumulator (persistent), 16x32 per warp
    float rsum[2] = {0.f, 0.f};

    for (int jt = 0; jt < 16; jt++) {
        const int cur = jt & 1;
        const int j0 = jt * 128;
        cp_wait_all();
        __syncthreads();                       // K/V[cur] ready; prev PV done with Ps
        if (jt + 1 < 16) { load_kv(jt + 1, cur ^ 1); cp_commit(); }

        // ---- pack mask tile into bits (512 words); 32 words per warp ----
        for (int t0 = 0; t0 < 32; t0 += 8) {
            int mv[8];
#pragma unroll
            for (int u = 0; u < 8; u++) {
                int w = wid * 32 + t0 + u;
                int r = w >> 2, c32 = w & 3;
                mv[u] = mask[((size_t)bb * L + i0 + r) * L + j0 + c32 * 32 + lane];
            }
#pragma unroll
            for (int u = 0; u < 8; u++) {
                unsigned bal = __ballot_sync(0xffffffffu, mv[u] != 0);
                if (lane == 0) mbits[wid * 32 + t0 + u] = bal;
            }
        }

        // ---- S = Q @ K^T  (16 x 64 per warp) ----
        float sacc[8][4] = {};
        const float* Kt = sm + (cur ? KS_OFF1 : KS_OFF0);
#pragma unroll
        for (int ks = 0; ks < 8; ks++) {
            uint32_t bf[8][2];
#pragma unroll
            for (int ni = 0; ni < 8; ni++) {
                bf[ni][0] = asu(Kt[(wn0 + ni * 8 + g) * 68 + ks * 8 + tp]);
                bf[ni][1] = asu(Kt[(wn0 + ni * 8 + g) * 68 + ks * 8 + tp + 4]);
            }
#pragma unroll
            for (int ni = 0; ni < 8; ni++)
                mma_tf32(sacc[ni], qf[ks], bf[ni]);
        }
        __syncthreads();                       // mbits visible; Ps free

        // ---- E = mask ? exp(S) : 0 ; tf32-round; store to Ps; rowsum ----
        {
            int r0 = wm0 + g;
            int r1 = r0 + 8;
            uint32_t w0a = mbits[r0 * 4 + (wn0 >> 5)];
            uint32_t w0b = mbits[r0 * 4 + (wn0 >> 5) + 1];
            uint32_t w1a = mbits[r1 * 4 + (wn0 >> 5)];
            uint32_t w1b = mbits[r1 * 4 + (wn0 >> 5) + 1];
#pragma unroll
            for (int ni = 0; ni < 8; ni++) {
                int c = wn0 + ni * 8 + tp * 2;
                uint32_t w0 = (ni < 4) ? w0a : w0b;
                uint32_t w1 = (ni < 4) ? w1a : w1b;
                int sh = c & 31;
                float e00 = ((w0 >> sh) & 1u)       ? __expf(sacc[ni][0]) : 0.f;
                float e01 = ((w0 >> (sh + 1)) & 1u) ? __expf(sacc[ni][1]) : 0.f;
                float e10 = ((w1 >> sh) & 1u)       ? __expf(sacc[ni][2]) : 0.f;
                float e11 = ((w1 >> (sh + 1)) & 1u) ? __expf(sacc[ni][3]) : 0.f;
                e00 = __uint_as_float(f2tf32(e00));
                e01 = __uint_as_float(f2tf32(e01));
                e10 = __uint_as_float(f2tf32(e10));
                e11 = __uint_as_float(f2tf32(e11));
                rsum[0] += e00 + e01;
                rsum[1] += e10 + e11;
                *(float2*)&Ps[r0 * PSTR + c] = make_float2(e00, e01);
                *(float2*)&Ps[r1 * PSTR + c] = make_float2(e10, e11);
            }
        }
        __syncthreads();                       // full P tile ready

        // ---- coalesced copy P -> gmem attn (unnormalized) ----
        for (int t = tid; t < 4096; t += 512) {        // 128 rows x 32 float4
            int r = t >> 5, c4 = t & 31;
            *(float4*)&attnb[(size_t)(i0 + r) * L + j0 + c4 * 4] =
                *(float4*)&Ps[r * PSTR + c4 * 4];
        }

        // ---- ctx += P @ V  (16 x 32 per warp) ----
        const float* Vt = sm + (cur ? VS_OFF1 : VS_OFF0);
#pragma unroll
        for (int kp = 0; kp < 16; kp++) {
            uint32_t af[4], bf2[4][2];
            {
                int r = wm0 + g;
                af[0] = asu(Ps[r * PSTR + kp * 8 + tp]);
                af[1] = asu(Ps[(r + 8) * PSTR + kp * 8 + tp]);
                af[2] = asu(Ps[r * PSTR + kp * 8 + tp + 4]);
                af[3] = asu(Ps[(r + 8) * PSTR + kp * 8 + tp + 4]);
            }
#pragma unroll
            for (int ni = 0; ni < 4; ni++) {
                bf2[ni][0] = asu(Vt[(kp * 8 + tp) * 72 + wn0p + ni * 8 + g]);
                bf2[ni][1] = asu(Vt[(kp * 8 + tp + 4) * 72 + wn0p + ni * 8 + g]);
            }
#pragma unroll
            for (int ni = 0; ni < 4; ni++)
                mma_tf32(cv[ni], af, bf2[ni]);
        }
    }

    // ---- rowsum reduction (quad lanes tp=0..3 hold same rows) ----
#pragma unroll
    for (int s = 0; s < 2; s++) {
        rsum[s] += __shfl_xor_sync(0xffffffffu, rsum[s], 1);
        rsum[s] += __shfl_xor_sync(0xffffffffu, rsum[s], 2);
    }
    if (tp == 0) {
        atomicAdd(&rowsum_s[wm0 + g],     rsum[0]);
        atomicAdd(&rowsum_s[wm0 + g + 8], rsum[1]);
    }
    __syncthreads();
    if (tid < 128) inv_s[tid] = 1.0f / rowsum_s[tid];
    __syncthreads();

    // ---- write ctx (normalized) ----
    float* ctxb = ctx + (size_t)hb * L * DK;
    {
        int r0 = wm0 + g;
        float iv0 = inv_s[r0], iv1 = inv_s[r0 + 8];
#pragma unroll
        for (int ni = 0; ni < 4; ni++) {
            int c = wn0p + ni * 8 + tp * 2;
            *(float2*)&ctxb[(size_t)(i0 + r0) * DK + c] =
                make_float2(cv[ni][0] * iv0, cv[ni][1] * iv0);
            *(float2*)&ctxb[(size_t)(i0 + r0 + 8) * DK + c] =
                make_float2(cv[ni][2] * iv1, cv[ni][3] * iv1);
        }
    }

    // ---- rescale attn block in gmem (L2-warm) ----
    for (int t = tid; t < 128 * 512; t += 512) {       // 128 rows x 512 float4
        int r = t >> 9, c4 = t & 511;
        float iv = inv_s[r];
        float4 v = *(float4*)&attnb[(size_t)(i0 + r) * L + c4 * 4];
        v.x *= iv; v.y *= iv; v.z *= iv; v.w *= iv;
        *(float4*)&attnb[(size_t)(i0 + r) * L + c4 * 4] = v;
    }
}

// ---------------------------------------------------------------------------
// K3: out = gather(ctx) @ Wo + bo + residual(q).  64x64 tile, 4x4/thr.
// ---------------------------------------------------------------------------
__global__ void outproj_kernel(const float* __restrict__ ctx,
                               const float* __restrict__ Wo,
                               const float* __restrict__ bo,
                               const float* __restrict__ resid,
                               float* __restrict__ outp) {
    __shared__ float As[32][68];
    __shared__ float Bs[32][68];
    const int m0 = blockIdx.y * 64;
    const int n0 = blockIdx.x * 64;
    const int tid = threadIdx.x;
    const int tx = tid & 15, ty = tid >> 4;
    float acc[4][4] = {};
    for (int k0 = 0; k0 < DM; k0 += 32) {
#pragma unroll
        for (int t = 0; t < 8; t++) {
            int idx = tid + t * 256;
            int r = idx >> 5, c = idx & 31;
            int m = m0 + r;
            int gc = k0 + c;
            int h = gc >> 6, d = gc & 63;
            int bb = m >> 11, ii = m & (L - 1);
            As[c][r] = ctx[((size_t)(h * B + bb) * L + ii) * DK + d];
        }
#pragma unroll
        for (int t = 0; t < 8; t++) {
            int idx = tid + t * 256;
            int r = idx >> 6, c = idx & 63;
            Bs[r][c] = Wo[(size_t)(k0 + r) * DM + (n0 + c)];
        }
        __syncthreads();
#pragma unroll
        for (int kk = 0; kk < 32; kk++) {
            float4 av = *(const float4*)&As[kk][ty * 4];
            float4 bv = *(const float4*)&Bs[kk][tx * 4];
            float a[4] = {av.x, av.y, av.z, av.w};
            float b[4] = {bv.x, bv.y, bv.z, bv.w};
#pragma unroll
            for (int i = 0; i < 4; i++)
#pragma unroll
                for (int j = 0; j < 4; j++)
                    acc[i][j] = fmaf(a[i], b[j], acc[i][j]);
        }
        __syncthreads();
    }
#pragma unroll
    for (int i = 0; i < 4; i++) {
        int m = m0 + ty * 4 + i;
#pragma unroll
        for (int j = 0; j < 4; j++) {
            int n = n0 + tx * 4 + j;
            outp[(size_t)m * DM + n] = acc[i][j] + bo[n] + resid[(size_t)m * DM + n];
        }
    }
}

// ---------------------------------------------------------------------------
extern "C" void kernel_launch(void* const* d_in, const int* in_sizes, int n_in,
                              void* d_out, int out_size) {
    const float* q    = (const float*)d_in[0];
    const float* k    = (const float*)d_in[1];
    const float* v    = (const float*)d_in[2];
    const int*   mask = (const int*)  d_in[3];
    const float* Wq   = (const float*)d_in[4];
    const float* bq   = (const float*)d_in[5];
    const float* Wk   = (const float*)d_in[6];
    const float* bk   = (const float*)d_in[7];
    const float* Wv   = (const float*)d_in[8];
    const float* bv   = (const float*)d_in[9];
    const float* Wo   = (const float*)d_in[10];
    const float* bo   = (const float*)d_in[11];
    float* outp = (float*)d_out;

    float *Qh, *Kh, *Vh, *Ctx, *AttnFB;
    cudaGetSymbolAddress((void**)&Qh,     g_Qh);
    cudaGetSymbolAddress((void**)&Kh,     g_Kh);
    cudaGetSymbolAddress((void**)&Vh,     g_Vh);
    cudaGetSymbolAddress((void**)&Ctx,    g_ctx);
    cudaGetSymbolAddress((void**)&AttnFB, g_attn_fallback);

    float* attn = ((long long)out_size >= OUT_ELEMS + ATTN_ELEMS)
                      ? (outp + OUT_ELEMS) : AttnFB;

    cudaFuncSetAttribute(fused_attn_kernel,
                         cudaFuncAttributeMaxDynamicSharedMemorySize, SMEM_BYTES);

    const dim3 blk(256);
    const float inv_dk = 1.0f / 64.0f;     // temperature = d_k

    proj_kernel<<<dim3(DM / 64, (B * L) / 64), blk>>>(q, Wq, bq, Qh, inv_dk);
    proj_kernel<<<dim3(DM / 64, (B * L) / 64), blk>>>(k, Wk, bk, Kh, 1.0f);
    proj_kernel<<<dim3(DM / 64, (B * L) / 64), blk>>>(v, Wv, bv, Vh, 1.0f);

    fused_attn_kernel<<<dim3(L / 128, HB), dim3(512), SMEM_BYTES>>>(Qh, Kh, Vh, mask, attn, Ctx);

    outproj_kernel<<<dim3(DM / 64, (B * L) / 64), blk>>>(Ctx, Wo, bo, q, outp);
}

// round 9
// speedup vs baseline: 1.3436x; 1.0229x over previous
#include <cuda_runtime.h>
#include <cstdint>

// ---------------------------------------------------------------------------
// MultiHeadAttention, B=2, L=2048, H=8, d=64, d_model=512
// Round 8: fused attention de-MUFU'd (exp -> FMA Taylor poly, __expf was the
//          binding pipe at 67M EX2 ~ 440us) + two-sweep normalization
//          (sweep1: S+rowsum; sweep2: recompute S, write normalized attn once,
//          PV with normalized P). Kills the 512MB rescale round-trip.
// ---------------------------------------------------------------------------

namespace {
constexpr int B  = 2;
constexpr int L  = 2048;
constexpr int DK = 64;
constexpr int DM = 512;
constexpr int HB = 16;                                    // NH * B
constexpr long long OUT_ELEMS  = (long long)B * L * DM;
constexpr long long ATTN_ELEMS = (long long)HB * L * L;

// fused-kernel smem layout (float offsets)
constexpr int PSTR    = 132;      // P tile stride (128 cols + pad)
constexpr int PS_OFF  = 0;        // P / Q-staging: 128 x 132 = 16896
constexpr int KS_OFF0 = 16896;    // K tile: 128 x 68
constexpr int KS_OFF1 = 25600;
constexpr int VS_OFF0 = 34304;    // V tile: 128 x 72
constexpr int VS_OFF1 = 43520;
constexpr int MB_OFF  = 52736;    // 512 uint32 mask bits
constexpr int RS_OFF  = 53248;    // rowsum[128]
constexpr int INV_OFF = 53376;    // inv[128]
constexpr int SMEM_FLOATS = 53504;
constexpr int SMEM_BYTES  = SMEM_FLOATS * 4;   // 214016 < 227KB cap
}

// Scratch (__device__ globals; addresses resolved via cudaGetSymbolAddress)
__device__ float g_Qh[HB * L * DK];   // tf32-rounded, pre-scaled by 1/64
__device__ float g_Kh[HB * L * DK];   // tf32-rounded
__device__ float g_Vh[HB * L * DK];   // tf32-rounded
__device__ float g_ctx[HB * L * DK];
__device__ float g_attn_fallback[(size_t)HB * L * L];

// ---------------------------------------------------------------------------
__device__ __forceinline__ uint32_t f2tf32(float f) {
    uint32_t u;
    asm("cvt.rna.tf32.f32 %0, %1;" : "=r"(u) : "f"(f));
    return u;
}
__device__ __forceinline__ void mma_tf32(float* c, const uint32_t* a, const uint32_t* b) {
    asm volatile(
        "mma.sync.aligned.m16n8k8.row.col.f32.tf32.tf32.f32 "
        "{%0,%1,%2,%3},{%4,%5,%6,%7},{%8,%9},{%0,%1,%2,%3};"
        : "+f"(c[0]), "+f"(c[1]), "+f"(c[2]), "+f"(c[3])
        : "r"(a[0]), "r"(a[1]), "r"(a[2]), "r"(a[3]), "r"(b[0]), "r"(b[1]));
}
__device__ __forceinline__ void cp_async16(void* sdst, const void* gsrc) {
    uint32_t da = (uint32_t)__cvta_generic_to_shared(sdst);
    asm volatile("cp.async.cg.shared.global [%0], [%1], 16;" :: "r"(da), "l"(gsrc));
}
__device__ __forceinline__ void cp_commit() { asm volatile("cp.async.commit_group;"); }
__device__ __forceinline__ void cp_wait_all() { asm volatile("cp.async.wait_group 0;"); }
__device__ __forceinline__ uint32_t asu(float f) { return __float_as_uint(f); }

// exp via FMA Taylor-6 (|x| <= ~0.6: rel err < 5e-7; scores here are |x|<0.3).
__device__ __forceinline__ float exp_poly(float x) {
    float r = 1.38888894e-3f;            // 1/720
    r = fmaf(r, x, 8.33333377e-3f);      // 1/120
    r = fmaf(r, x, 4.16666679e-2f);      // 1/24
    r = fmaf(r, x, 1.66666672e-1f);      // 1/6
    r = fmaf(r, x, 0.5f);
    r = fmaf(r, x, 1.0f);
    r = fmaf(r, x, 1.0f);
    return r;
}
// 4 exps with warp-uniform rare fallback to MUFU (branched around, not predicated)
__device__ __forceinline__ void exp4(const float* s, float* e) {
    e[0] = exp_poly(s[0]); e[1] = exp_poly(s[1]);
    e[2] = exp_poly(s[2]); e[3] = exp_poly(s[3]);
    float mx = fmaxf(fmaxf(fabsf(s[0]), fabsf(s[1])), fmaxf(fabsf(s[2]), fabsf(s[3])));
    if (__any_sync(0xffffffffu, mx > 0.6f)) {
        e[0] = __expf(s[0]); e[1] = __expf(s[1]);
        e[2] = __expf(s[2]); e[3] = __expf(s[3]);
    }
}

// ---------------------------------------------------------------------------
// K1: projection GEMM. out[h*B+b][i][d] = tf32(((A@W)[n] + bias[n]) * alpha)
// ---------------------------------------------------------------------------
__global__ void proj_kernel(const float* __restrict__ A,
                            const float* __restrict__ W,
                            const float* __restrict__ bias,
                            float* __restrict__ outp,
                            float alpha) {
    __shared__ float As[32][68];
    __shared__ float Bs[32][68];
    const int m0 = blockIdx.y * 64;
    const int n0 = blockIdx.x * 64;
    const int tid = threadIdx.x;
    const int tx = tid & 15, ty = tid >> 4;
    float acc[4][4] = {};
    for (int k0 = 0; k0 < DM; k0 += 32) {
#pragma unroll
        for (int t = 0; t < 8; t++) {
            int idx = tid + t * 256;
            int r = idx >> 5, c = idx & 31;
            As[c][r] = A[(size_t)(m0 + r) * DM + (k0 + c)];
        }
#pragma unroll
        for (int t = 0; t < 8; t++) {
            int idx = tid + t * 256;
            int r = idx >> 6, c = idx & 63;
            Bs[r][c] = W[(size_t)(k0 + r) * DM + (n0 + c)];
        }
        __syncthreads();
#pragma unroll
        for (int kk = 0; kk < 32; kk++) {
            float4 av = *(const float4*)&As[kk][ty * 4];
            float4 bv = *(const float4*)&Bs[kk][tx * 4];
            float a[4] = {av.x, av.y, av.z, av.w};
            float b[4] = {bv.x, bv.y, bv.z, bv.w};
#pragma unroll
            for (int i = 0; i < 4; i++)
#pragma unroll
                for (int j = 0; j < 4; j++)
                    acc[i][j] = fmaf(a[i], b[j], acc[i][j]);
        }
        __syncthreads();
    }
#pragma unroll
    for (int i = 0; i < 4; i++) {
        int m  = m0 + ty * 4 + i;
        int bb = m >> 11, ii = m & (L - 1);
#pragma unroll
        for (int j = 0; j < 4; j++) {
            int n = n0 + tx * 4 + j;
            int h = n >> 6, d = n & 63;
            float val = (acc[i][j] + bias[n]) * alpha;
            outp[((size_t)(h * B + bb) * L + ii) * DK + d] = __uint_as_float(f2tf32(val));
        }
    }
}

// ---------------------------------------------------------------------------
// K2: fused attention, two-sweep.  grid (16, 16), 512 threads, 1 CTA/SM.
// ---------------------------------------------------------------------------
__global__ __launch_bounds__(512, 1)
void fused_attn_kernel(const float* __restrict__ Qh,
                       const float* __restrict__ Kh,
                       const float* __restrict__ Vh,
                       const int*   __restrict__ mask,
                       float* __restrict__ attn,
                       float* __restrict__ ctx) {
    extern __shared__ float sm[];
    float* Ps = sm + PS_OFF;                  // 128 x PSTR
    uint32_t* mbits = (uint32_t*)(sm + MB_OFF);
    float* rowsum_s = sm + RS_OFF;
    float* inv_s    = sm + INV_OFF;

    const int i0 = blockIdx.x * 128;
    const int hb = blockIdx.y;
    const int bb = hb & (B - 1);
    const int tid = threadIdx.x;
    const int wid = tid >> 5, lane = tid & 31;
    const int g = lane >> 2, tp = lane & 3;
    const int wm0  = (wid >> 1) * 16;       // 16 M-rows per warp
    const int wn0  = (wid & 1) * 64;        // N range for S (64 wide)
    const int wn0p = (wid & 1) * 32;        // N range for PV (32 wide)

    const float* Qb = Qh + (size_t)hb * L * DK;
    const float* Kb = Kh + (size_t)hb * L * DK;
    const float* Vb = Vh + (size_t)hb * L * DK;
    float* attnb = attn + (size_t)hb * L * L;

    if (tid < 128) rowsum_s[tid] = 0.f;

    // ---- stage Q into Ps, extract A-fragments to registers ----
    for (int t = tid; t < 2048; t += 512) {
        int r = t >> 4, c4 = t & 15;
        *(float4*)&Ps[r * PSTR + c4 * 4] =
            *(const float4*)&Qb[(size_t)(i0 + r) * DK + c4 * 4];
    }
    __syncthreads();
    uint32_t qf[8][4];
    {
        int r = wm0 + g;
#pragma unroll
        for (int ks = 0; ks < 8; ks++) {
            qf[ks][0] = asu(Ps[r * PSTR + ks * 8 + tp]);
            qf[ks][1] = asu(Ps[(r + 8) * PSTR + ks * 8 + tp]);
            qf[ks][2] = asu(Ps[r * PSTR + ks * 8 + tp + 4]);
            qf[ks][3] = asu(Ps[(r + 8) * PSTR + ks * 8 + tp + 4]);
        }
    }
    __syncthreads();

    // ---- loaders ----
    auto load_k = [&](int jt, int buf) {
        const int j0 = jt * 128;
        float* Kd = sm + (buf ? KS_OFF1 : KS_OFF0);
        for (int t = tid; t < 2048; t += 512) {
            int r = t >> 4, c4 = t & 15;
            cp_async16(&Kd[r * 68 + c4 * 4], &Kb[(size_t)(j0 + r) * DK + c4 * 4]);
        }
    };
    auto load_kv = [&](int jt, int buf) {
        const int j0 = jt * 128;
        float* Kd = sm + (buf ? KS_OFF1 : KS_OFF0);
        float* Vd = sm + (buf ? VS_OFF1 : VS_OFF0);
        for (int t = tid; t < 2048; t += 512) {
            int r = t >> 4, c4 = t & 15;
            cp_async16(&Kd[r * 68 + c4 * 4], &Kb[(size_t)(j0 + r) * DK + c4 * 4]);
            cp_async16(&Vd[r * 72 + c4 * 4], &Vb[(size_t)(j0 + r) * DK + c4 * 4]);
        }
    };
    auto pack_mask = [&](int j0) {
        for (int t0 = 0; t0 < 32; t0 += 8) {
            int mv[8];
#pragma unroll
            for (int u = 0; u < 8; u++) {
                int w = wid * 32 + t0 + u;
                int r = w >> 2, c32 = w & 3;
                mv[u] = mask[((size_t)bb * L + i0 + r) * L + j0 + c32 * 32 + lane];
            }
#pragma unroll
            for (int u = 0; u < 8; u++) {
                unsigned bal = __ballot_sync(0xffffffffu, mv[u] != 0);
                if (lane == 0) mbits[wid * 32 + t0 + u] = bal;
            }
        }
    };

    // ================= SWEEP 1: rowsum only =================
    load_k(0, 0);
    cp_commit();
    float rsum[2] = {0.f, 0.f};

    for (int jt = 0; jt < 16; jt++) {
        const int cur = jt & 1;
        const int j0 = jt * 128;
        cp_wait_all();
        __syncthreads();
        if (jt + 1 < 16) { load_k(jt + 1, cur ^ 1); cp_commit(); }
        else             { load_kv(0, cur ^ 1);     cp_commit(); }  // prefetch sweep2 jt0 -> buf0

        pack_mask(j0);

        float sacc[8][4] = {};
        const float* Kt = sm + (cur ? KS_OFF1 : KS_OFF0);
#pragma unroll
        for (int ks = 0; ks < 8; ks++) {
            uint32_t bf[8][2];
#pragma unroll
            for (int ni = 0; ni < 8; ni++) {
                bf[ni][0] = asu(Kt[(wn0 + ni * 8 + g) * 68 + ks * 8 + tp]);
                bf[ni][1] = asu(Kt[(wn0 + ni * 8 + g) * 68 + ks * 8 + tp + 4]);
            }
#pragma unroll
            for (int ni = 0; ni < 8; ni++)
                mma_tf32(sacc[ni], qf[ks], bf[ni]);
        }
        __syncthreads();                       // mbits visible

        {
            int r0 = wm0 + g;
            int r1 = r0 + 8;
            uint32_t w0a = mbits[r0 * 4 + (wn0 >> 5)];
            uint32_t w0b = mbits[r0 * 4 + (wn0 >> 5) + 1];
            uint32_t w1a = mbits[r1 * 4 + (wn0 >> 5)];
            uint32_t w1b = mbits[r1 * 4 + (wn0 >> 5) + 1];
#pragma unroll
            for (int ni = 0; ni < 8; ni++) {
                int c = wn0 + ni * 8 + tp * 2;
                uint32_t w0 = (ni < 4) ? w0a : w0b;
                uint32_t w1 = (ni < 4) ? w1a : w1b;
                int sh = c & 31;
                float e[4];
                exp4(sacc[ni], e);
                float e00 = ((w0 >> sh) & 1u)       ? e[0] : 0.f;
                float e01 = ((w0 >> (sh + 1)) & 1u) ? e[1] : 0.f;
                float e10 = ((w1 >> sh) & 1u)       ? e[2] : 0.f;
                float e11 = ((w1 >> (sh + 1)) & 1u) ? e[3] : 0.f;
                rsum[0] += e00 + e01;
                rsum[1] += e10 + e11;
            }
        }
    }

    // ---- rowsum reduction -> inv ----
#pragma unroll
    for (int s = 0; s < 2; s++) {
        rsum[s] += __shfl_xor_sync(0xffffffffu, rsum[s], 1);
        rsum[s] += __shfl_xor_sync(0xffffffffu, rsum[s], 2);
    }
    if (tp == 0) {
        atomicAdd(&rowsum_s[wm0 + g],     rsum[0]);
        atomicAdd(&rowsum_s[wm0 + g + 8], rsum[1]);
    }
    __syncthreads();
    if (tid < 128) inv_s[tid] = 1.0f / rowsum_s[tid];
    __syncthreads();

    const float iv0 = inv_s[wm0 + g];
    const float iv1 = inv_s[wm0 + g + 8];

    // ================= SWEEP 2: write attn + PV =================
    float cv[4][4] = {};

    for (int jt = 0; jt < 16; jt++) {
        const int cur = jt & 1;
        const int j0 = jt * 128;
        cp_wait_all();
        __syncthreads();                       // K/V[cur] ready; Ps free (prev PV done)
        if (jt + 1 < 16) { load_kv(jt + 1, cur ^ 1); cp_commit(); }

        pack_mask(j0);

        float sacc[8][4] = {};
        const float* Kt = sm + (cur ? KS_OFF1 : KS_OFF0);
#pragma unroll
        for (int ks = 0; ks < 8; ks++) {
            uint32_t bf[8][2];
#pragma unroll
            for (int ni = 0; ni < 8; ni++) {
                bf[ni][0] = asu(Kt[(wn0 + ni * 8 + g) * 68 + ks * 8 + tp]);
                bf[ni][1] = asu(Kt[(wn0 + ni * 8 + g) * 68 + ks * 8 + tp + 4]);
            }
#pragma unroll
            for (int ni = 0; ni < 8; ni++)
                mma_tf32(sacc[ni], qf[ks], bf[ni]);
        }
        __syncthreads();                       // mbits visible; Ps free

        // exp, normalize, store fp32 P to smem AND gmem attn (final values)
        {
            int r0 = wm0 + g;
            int r1 = r0 + 8;
            uint32_t w0a = mbits[r0 * 4 + (wn0 >> 5)];
            uint32_t w0b = mbits[r0 * 4 + (wn0 >> 5) + 1];
            uint32_t w1a = mbits[r1 * 4 + (wn0 >> 5)];
            uint32_t w1b = mbits[r1 * 4 + (wn0 >> 5) + 1];
            float* arow0 = attnb + (size_t)(i0 + r0) * L + j0;
            float* arow1 = attnb + (size_t)(i0 + r1) * L + j0;
#pragma unroll
            for (int ni = 0; ni < 8; ni++) {
                int c = wn0 + ni * 8 + tp * 2;
                uint32_t w0 = (ni < 4) ? w0a : w0b;
                uint32_t w1 = (ni < 4) ? w1a : w1b;
                int sh = c & 31;
                float e[4];
                exp4(sacc[ni], e);
                float p00 = (((w0 >> sh) & 1u)       ? e[0] : 0.f) * iv0;
                float p01 = (((w0 >> (sh + 1)) & 1u) ? e[1] : 0.f) * iv0;
                float p10 = (((w1 >> sh) & 1u)       ? e[2] : 0.f) * iv1;
                float p11 = (((w1 >> (sh + 1)) & 1u) ? e[3] : 0.f) * iv1;
                *(float2*)&Ps[r0 * PSTR + c] = make_float2(p00, p01);
                *(float2*)&Ps[r1 * PSTR + c] = make_float2(p10, p11);
                *(float2*)&arow0[c] = make_float2(p00, p01);
                *(float2*)&arow1[c] = make_float2(p10, p11);
            }
        }
        __syncthreads();                       // full P tile ready

        // ---- ctx += P_norm @ V ----
        const float* Vt = sm + (cur ? VS_OFF1 : VS_OFF0);
#pragma unroll
        for (int kp = 0; kp < 16; kp++) {
            uint32_t af[4], bf2[4][2];
            {
                int r = wm0 + g;
                af[0] = f2tf32(Ps[r * PSTR + kp * 8 + tp]);
                af[1] = f2tf32(Ps[(r + 8) * PSTR + kp * 8 + tp]);
                af[2] = f2tf32(Ps[r * PSTR + kp * 8 + tp + 4]);
                af[3] = f2tf32(Ps[(r + 8) * PSTR + kp * 8 + tp + 4]);
            }
#pragma unroll
            for (int ni = 0; ni < 4; ni++) {
                bf2[ni][0] = asu(Vt[(kp * 8 + tp) * 72 + wn0p + ni * 8 + g]);
                bf2[ni][1] = asu(Vt[(kp * 8 + tp + 4) * 72 + wn0p + ni * 8 + g]);
            }
#pragma unroll
            for (int ni = 0; ni < 4; ni++)
                mma_tf32(cv[ni], af, bf2[ni]);
        }
    }

    // ---- write ctx (already normalized) ----
    float* ctxb = ctx + (size_t)hb * L * DK;
    {
        int r0 = wm0 + g;
#pragma unroll
        for (int ni = 0; ni < 4; ni++) {
            int c = wn0p + ni * 8 + tp * 2;
            *(float2*)&ctxb[(size_t)(i0 + r0) * DK + c] =
                make_float2(cv[ni][0], cv[ni][1]);
            *(float2*)&ctxb[(size_t)(i0 + r0 + 8) * DK + c] =
                make_float2(cv[ni][2], cv[ni][3]);
        }
    }
}

// ---------------------------------------------------------------------------
// K3: out = gather(ctx) @ Wo + bo + residual(q).  64x64 tile, 4x4/thr.
// ---------------------------------------------------------------------------
__global__ void outproj_kernel(const float* __restrict__ ctx,
                               const float* __restrict__ Wo,
                               const float* __restrict__ bo,
                               const float* __restrict__ resid,
                               float* __restrict__ outp) {
    __shared__ float As[32][68];
    __shared__ float Bs[32][68];
    const int m0 = blockIdx.y * 64;
    const int n0 = blockIdx.x * 64;
    const int tid = threadIdx.x;
    const int tx = tid & 15, ty = tid >> 4;
    float acc[4][4] = {};
    for (int k0 = 0; k0 < DM; k0 += 32) {
#pragma unroll
        for (int t = 0; t < 8; t++) {
            int idx = tid + t * 256;
            int r = idx >> 5, c = idx & 31;
            int m = m0 + r;
            int gc = k0 + c;
            int h = gc >> 6, d = gc & 63;
            int bb = m >> 11, ii = m & (L - 1);
            As[c][r] = ctx[((size_t)(h * B + bb) * L + ii) * DK + d];
        }
#pragma unroll
        for (int t = 0; t < 8; t++) {
            int idx = tid + t * 256;
            int r = idx >> 6, c = idx & 63;
            Bs[r][c] = Wo[(size_t)(k0 + r) * DM + (n0 + c)];
        }
        __syncthreads();
#pragma unroll
        for (int kk = 0; kk < 32; kk++) {
            float4 av = *(const float4*)&As[kk][ty * 4];
            float4 bv = *(const float4*)&Bs[kk][tx * 4];
            float a[4] = {av.x, av.y, av.z, av.w};
            float b[4] = {bv.x, bv.y, bv.z, bv.w};
#pragma unroll
            for (int i = 0; i < 4; i++)
#pragma unroll
                for (int j = 0; j < 4; j++)
                    acc[i][j] = fmaf(a[i], b[j], acc[i][j]);
        }
        __syncthreads();
    }
#pragma unroll
    for (int i = 0; i < 4; i++) {
        int m = m0 + ty * 4 + i;
#pragma unroll
        for (int j = 0; j < 4; j++) {
            int n = n0 + tx * 4 + j;
            outp[(size_t)m * DM + n] = acc[i][j] + bo[n] + resid[(size_t)m * DM + n];
        }
    }
}

// ---------------------------------------------------------------------------
extern "C" void kernel_launch(void* const* d_in, const int* in_sizes, int n_in,
                              void* d_out, int out_size) {
    const float* q    = (const float*)d_in[0];
    const float* k    = (const float*)d_in[1];
    const float* v    = (const float*)d_in[2];
    const int*   mask = (const int*)  d_in[3];
    const float* Wq   = (const float*)d_in[4];
    const float* bq   = (const float*)d_in[5];
    const float* Wk   = (const float*)d_in[6];
    const float* bk   = (const float*)d_in[7];
    const float* Wv   = (const float*)d_in[8];
    const float* bv   = (const float*)d_in[9];
    const float* Wo   = (const float*)d_in[10];
    const float* bo   = (const float*)d_in[11];
    float* outp = (float*)d_out;

    float *Qh, *Kh, *Vh, *Ctx, *AttnFB;
    cudaGetSymbolAddress((void**)&Qh,     g_Qh);
    cudaGetSymbolAddress((void**)&Kh,     g_Kh);
    cudaGetSymbolAddress((void**)&Vh,     g_Vh);
    cudaGetSymbolAddress((void**)&Ctx,    g_ctx);
    cudaGetSymbolAddress((void**)&AttnFB, g_attn_fallback);

    float* attn = ((long long)out_size >= OUT_ELEMS + ATTN_ELEMS)
                      ? (outp + OUT_ELEMS) : AttnFB;

    cudaFuncSetAttribute(fused_attn_kernel,
                         cudaFuncAttributeMaxDynamicSharedMemorySize, SMEM_BYTES);

    const dim3 blk(256);
    const float inv_dk = 1.0f / 64.0f;     // temperature = d_k

    proj_kernel<<<dim3(DM / 64, (B * L) / 64), blk>>>(q, Wq, bq, Qh, inv_dk);
    proj_kernel<<<dim3(DM / 64, (B * L) / 64), blk>>>(k, Wk, bk, Kh, 1.0f);
    proj_kernel<<<dim3(DM / 64, (B * L) / 64), blk>>>(v, Wv, bv, Vh, 1.0f);

    fused_attn_kernel<<<dim3(L / 128, HB), dim3(512), SMEM_BYTES>>>(Qh, Kh, Vh, mask, attn, Ctx);

    outproj_kernel<<<dim3(DM / 64, (B * L) / 64), blk>>>(Ctx, Wo, bo, q, outp);
}

// round 10
// speedup vs baseline: 2.4377x; 1.8143x over previous
#include <cuda_runtime.h>
#include <cstdint>

// ---------------------------------------------------------------------------
// MultiHeadAttention, B=2, L=2048, H=8, d=64, d_model=512
// Round 9: (a) all projections + outproj moved to tf32 mma (weights
//          pre-transposed+rounded once); (b) mask pre-packed to bits once,
//          fused kernel loads 4 broadcast words/tile instead of 32 LDG+ballot.
// ---------------------------------------------------------------------------

namespace {
constexpr int B  = 2;
constexpr int L  = 2048;
constexpr int DK = 64;
constexpr int DM = 512;
constexpr int HB = 16;                                    // NH * B
constexpr long long OUT_ELEMS  = (long long)B * L * DM;
constexpr long long ATTN_ELEMS = (long long)HB * L * L;

// fused-kernel smem layout (float offsets)
constexpr int PSTR    = 132;
constexpr int PS_OFF  = 0;        // 128 x 132
constexpr int KS_OFF0 = 16896;    // K tile 128 x 68
constexpr int KS_OFF1 = 25600;
constexpr int VS_OFF0 = 34304;    // V tile 128 x 72
constexpr int VS_OFF1 = 43520;
constexpr int RS_OFF  = 52736;    // rowsum[128]
constexpr int INV_OFF = 52864;    // inv[128]
constexpr int SMEM_FLOATS = 52992;
constexpr int SMEM_BYTES  = SMEM_FLOATS * 4;   // 211968

// proj-kernel smem layout (float offsets): A 128x68 x2, B 64x68 x2
constexpr int PJ_AS0 = 0;
constexpr int PJ_AS1 = 8704;
constexpr int PJ_BS0 = 17408;
constexpr int PJ_BS1 = 21760;
constexpr int PJ_FLOATS = 26112;
constexpr int PJ_BYTES  = PJ_FLOATS * 4;       // 104448 -> 2 CTA/SM
}

// Scratch (__device__ globals)
__device__ float g_Qh[HB * L * DK];
__device__ float g_Kh[HB * L * DK];
__device__ float g_Vh[HB * L * DK];
__device__ float g_ctx[HB * L * DK];
__device__ float g_WT[4 * DM * DM];                 // tf32 W^T: Wq,Wk,Wv,Wo
__device__ uint32_t g_mbits[(size_t)B * L * (L / 32)];  // packed mask bits
__device__ float g_attn_fallback[(size_t)HB * L * L];

// ---------------------------------------------------------------------------
__device__ __forceinline__ uint32_t f2tf32(float f) {
    uint32_t u;
    asm("cvt.rna.tf32.f32 %0, %1;" : "=r"(u) : "f"(f));
    return u;
}
__device__ __forceinline__ void mma_tf32(float* c, const uint32_t* a, const uint32_t* b) {
    asm volatile(
        "mma.sync.aligned.m16n8k8.row.col.f32.tf32.tf32.f32 "
        "{%0,%1,%2,%3},{%4,%5,%6,%7},{%8,%9},{%0,%1,%2,%3};"
        : "+f"(c[0]), "+f"(c[1]), "+f"(c[2]), "+f"(c[3])
        : "r"(a[0]), "r"(a[1]), "r"(a[2]), "r"(a[3]), "r"(b[0]), "r"(b[1]));
}
__device__ __forceinline__ void cp_async16(void* sdst, const void* gsrc) {
    uint32_t da = (uint32_t)__cvta_generic_to_shared(sdst);
    asm volatile("cp.async.cg.shared.global [%0], [%1], 16;" :: "r"(da), "l"(gsrc));
}
__device__ __forceinline__ void cp_commit() { asm volatile("cp.async.commit_group;"); }
__device__ __forceinline__ void cp_wait_all() { asm volatile("cp.async.wait_group 0;"); }
__device__ __forceinline__ uint32_t asu(float f) { return __float_as_uint(f); }

// exp via FMA Taylor-6 (|x| < ~0.6 here; rare warp-uniform MUFU fallback).
__device__ __forceinline__ float exp_poly(float x) {
    float r = 1.38888894e-3f;
    r = fmaf(r, x, 8.33333377e-3f);
    r = fmaf(r, x, 4.16666679e-2f);
    r = fmaf(r, x, 1.66666672e-1f);
    r = fmaf(r, x, 0.5f);
    r = fmaf(r, x, 1.0f);
    r = fmaf(r, x, 1.0f);
    return r;
}
__device__ __forceinline__ void exp4(const float* s, float* e) {
    e[0] = exp_poly(s[0]); e[1] = exp_poly(s[1]);
    e[2] = exp_poly(s[2]); e[3] = exp_poly(s[3]);
    float mx = fmaxf(fmaxf(fabsf(s[0]), fabsf(s[1])), fmaxf(fabsf(s[2]), fabsf(s[3])));
    if (__any_sync(0xffffffffu, mx > 0.6f)) {
        e[0] = __expf(s[0]); e[1] = __expf(s[1]);
        e[2] = __expf(s[2]); e[3] = __expf(s[3]);
    }
}

// ---------------------------------------------------------------------------
// K0a: transpose + tf32-round the 4 weight matrices: WT[n][k] = tf32(W[k][n])
// ---------------------------------------------------------------------------
__global__ void transpose_w_kernel(const float* __restrict__ W0,
                                   const float* __restrict__ W1,
                                   const float* __restrict__ W2,
                                   const float* __restrict__ W3,
                                   float* __restrict__ outT) {
    __shared__ float t[32][33];
    const float* W = (blockIdx.z == 0) ? W0 : (blockIdx.z == 1) ? W1
                   : (blockIdx.z == 2) ? W2 : W3;
    float* o = outT + (size_t)blockIdx.z * DM * DM;
    const int k0 = blockIdx.y * 32, n0 = blockIdx.x * 32;
    const int tx = threadIdx.x, ty = threadIdx.y;
#pragma unroll
    for (int i = 0; i < 32; i += 8)
        t[ty + i][tx] = W[(size_t)(k0 + ty + i) * DM + n0 + tx];
    __syncthreads();
#pragma unroll
    for (int i = 0; i < 32; i += 8)
        o[(size_t)(n0 + ty + i) * DM + k0 + tx] =
            __uint_as_float(f2tf32(t[tx][ty + i]));
}

// ---------------------------------------------------------------------------
// K0b: pack mask to bits: one warp per 32-int word.
// ---------------------------------------------------------------------------
__global__ void maskbits_kernel(const int* __restrict__ mask,
                                uint32_t* __restrict__ out) {
    size_t w = (size_t)blockIdx.x * 8 + (threadIdx.x >> 5);
    int lane = threadIdx.x & 31;
    int m = mask[w * 32 + lane];
    unsigned bal = __ballot_sync(0xffffffffu, m != 0);
    if (lane == 0) out[w] = bal;
}

// ---------------------------------------------------------------------------
// K1: QKV projection via tf32 mma.  out[h*B+b][i][d] = tf32((A@W + b)*alpha)
//     NT gemm: A[m][k] row-major, WT[n][k] row-major (pre-tf32).
//     grid (N/64, M/128, 3), 256 thr, 8 warps (4M x 2N), warp 32x32.
// ---------------------------------------------------------------------------
__global__ __launch_bounds__(256, 2)
void proj_mma_kernel(const float* __restrict__ q, const float* __restrict__ k,
                     const float* __restrict__ v, const float* __restrict__ WT,
                     const float* __restrict__ bq, const float* __restrict__ bk,
                     const float* __restrict__ bv,
                     float* __restrict__ Qh, float* __restrict__ Kh,
                     float* __restrict__ Vh, float inv_dk) {
    extern __shared__ float smp[];
    const int z = blockIdx.z;
    const float* A    = (z == 0) ? q  : (z == 1) ? k  : v;
    const float* BT   = WT + (size_t)z * DM * DM;
    const float* bias = (z == 0) ? bq : (z == 1) ? bk : bv;
    float* outp       = (z == 0) ? Qh : (z == 1) ? Kh : Vh;
    const float alpha = (z == 0) ? inv_dk : 1.0f;

    const int m0 = blockIdx.y * 128;
    const int n0 = blockIdx.x * 64;
    const int tid = threadIdx.x;
    const int wid = tid >> 5, lane = tid & 31;
    const int g = lane >> 2, tp = lane & 3;
    const int wm0 = (wid >> 1) * 32;
    const int wn0 = (wid & 1) * 32;

    auto load_chunk = [&](int kc, int buf) {
        float* As = smp + (buf ? PJ_AS1 : PJ_AS0);
        float* Bs = smp + (buf ? PJ_BS1 : PJ_BS0);
        const int k0 = kc * 64;
        for (int t = tid; t < 2048; t += 256) {
            int r = t >> 4, c4 = t & 15;
            cp_async16(&As[r * 68 + c4 * 4], &A[(size_t)(m0 + r) * DM + k0 + c4 * 4]);
        }
        for (int t = tid; t < 1024; t += 256) {
            int r = t >> 4, c4 = t & 15;
            cp_async16(&Bs[r * 68 + c4 * 4], &BT[(size_t)(n0 + r) * DM + k0 + c4 * 4]);
        }
    };
    load_chunk(0, 0);
    cp_commit();

    float cv[2][4][4] = {};
    for (int kc = 0; kc < 8; kc++) {
        cp_wait_all();
        __syncthreads();
        if (kc + 1 < 8) { load_chunk(kc + 1, (kc & 1) ^ 1); cp_commit(); }
        const float* As = smp + ((kc & 1) ? PJ_AS1 : PJ_AS0);
        const float* Bs = smp + ((kc & 1) ? PJ_BS1 : PJ_BS0);
#pragma unroll
        for (int ks = 0; ks < 8; ks++) {
            uint32_t af[2][4], bf[4][2];
#pragma unroll
            for (int mi = 0; mi < 2; mi++) {
                int r = wm0 + mi * 16 + g;
                af[mi][0] = f2tf32(As[r * 68 + ks * 8 + tp]);
                af[mi][1] = f2tf32(As[(r + 8) * 68 + ks * 8 + tp]);
                af[mi][2] = f2tf32(As[r * 68 + ks * 8 + tp + 4]);
                af[mi][3] = f2tf32(As[(r + 8) * 68 + ks * 8 + tp + 4]);
            }
#pragma unroll
            for (int ni = 0; ni < 4; ni++) {
                bf[ni][0] = asu(Bs[(wn0 + ni * 8 + g) * 68 + ks * 8 + tp]);
                bf[ni][1] = asu(Bs[(wn0 + ni * 8 + g) * 68 + ks * 8 + tp + 4]);
            }
#pragma unroll
            for (int mi = 0; mi < 2; mi++)
#pragma unroll
                for (int ni = 0; ni < 4; ni++)
                    mma_tf32(cv[mi][ni], af[mi], bf[ni]);
        }
    }

    // epilogue: scatter to [h*B+b][i][d], tf32-rounded
    const int hB = n0 >> 6;                 // head (n0 is 64-aligned)
#pragma unroll
    for (int mi = 0; mi < 2; mi++) {
        int m  = m0 + wm0 + mi * 16 + g;
        int bb = m >> 11, ii = m & (L - 1);
        size_t rb0 = ((size_t)(hB * B + bb) * L + ii) * DK;
        size_t rb1 = rb0 + 8 * DK;
#pragma unroll
        for (int ni = 0; ni < 4; ni++) {
            int d = wn0 + ni * 8 + tp * 2;
            int n = n0 + d;
            float b0 = bias[n], b1 = bias[n + 1];
            float2 v0 = make_float2(
                __uint_as_float(f2tf32((cv[mi][ni][0] + b0) * alpha)),
                __uint_as_float(f2tf32((cv[mi][ni][1] + b1) * alpha)));
            float2 v1 = make_float2(
                __uint_as_float(f2tf32((cv[mi][ni][2] + b0) * alpha)),
                __uint_as_float(f2tf32((cv[mi][ni][3] + b1) * alpha)));
            *(float2*)&outp[rb0 + d] = v0;
            *(float2*)&outp[rb1 + d] = v1;
        }
    }
}

// ---------------------------------------------------------------------------
// K3: output projection via tf32 mma: out = gather(ctx) @ Wo + bo + resid.
//     A rows gathered from ctx ([h][bb][ii][d], h = k-chunk index).
// ---------------------------------------------------------------------------
__global__ __launch_bounds__(256, 2)
void outproj_mma_kernel(const float* __restrict__ ctx,
                        const float* __restrict__ WoT,
                        const float* __restrict__ bo,
                        const float* __restrict__ resid,
                        float* __restrict__ outp) {
    extern __shared__ float smp[];
    const int m0 = blockIdx.y * 128;
    const int n0 = blockIdx.x * 64;
    const int tid = threadIdx.x;
    const int wid = tid >> 5, lane = tid & 31;
    const int g = lane >> 2, tp = lane & 3;
    const int wm0 = (wid >> 1) * 32;
    const int wn0 = (wid & 1) * 32;

    auto load_chunk = [&](int kc, int buf) {
        float* As = smp + (buf ? PJ_AS1 : PJ_AS0);
        float* Bs = smp + (buf ? PJ_BS1 : PJ_BS0);
        for (int t = tid; t < 2048; t += 256) {
            int r = t >> 4, c4 = t & 15;
            int m = m0 + r, bb = m >> 11, ii = m & (L - 1);
            size_t base = ((size_t)(kc * B + bb) * L + ii) * DK;   // h = kc
            cp_async16(&As[r * 68 + c4 * 4], &ctx[base + c4 * 4]);
        }
        const int k0 = kc * 64;
        for (int t = tid; t < 1024; t += 256) {
            int r = t >> 4, c4 = t & 15;
            cp_async16(&Bs[r * 68 + c4 * 4], &WoT[(size_t)(n0 + r) * DM + k0 + c4 * 4]);
        }
    };
    load_chunk(0, 0);
    cp_commit();

    float cv[2][4][4] = {};
    for (int kc = 0; kc < 8; kc++) {
        cp_wait_all();
        __syncthreads();
        if (kc + 1 < 8) { load_chunk(kc + 1, (kc & 1) ^ 1); cp_commit(); }
        const float* As = smp + ((kc & 1) ? PJ_AS1 : PJ_AS0);
        const float* Bs = smp + ((kc & 1) ? PJ_BS1 : PJ_BS0);
#pragma unroll
        for (int ks = 0; ks < 8; ks++) {
            uint32_t af[2][4], bf[4][2];
#pragma unroll
            for (int mi = 0; mi < 2; mi++) {
                int r = wm0 + mi * 16 + g;
                af[mi][0] = f2tf32(As[r * 68 + ks * 8 + tp]);
                af[mi][1] = f2tf32(As[(r + 8) * 68 + ks * 8 + tp]);
                af[mi][2] = f2tf32(As[r * 68 + ks * 8 + tp + 4]);
                af[mi][3] = f2tf32(As[(r + 8) * 68 + ks * 8 + tp + 4]);
            }
#pragma unroll
            for (int ni = 0; ni < 4; ni++) {
                bf[ni][0] = asu(Bs[(wn0 + ni * 8 + g) * 68 + ks * 8 + tp]);
                bf[ni][1] = asu(Bs[(wn0 + ni * 8 + g) * 68 + ks * 8 + tp + 4]);
            }
#pragma unroll
            for (int mi = 0; mi < 2; mi++)
#pragma unroll
                for (int ni = 0; ni < 4; ni++)
                    mma_tf32(cv[mi][ni], af[mi], bf[ni]);
        }
    }

#pragma unroll
    for (int mi = 0; mi < 2; mi++) {
        int m = m0 + wm0 + mi * 16 + g;
#pragma unroll
        for (int ni = 0; ni < 4; ni++) {
            int n = n0 + wn0 + ni * 8 + tp * 2;
            float b0 = bo[n], b1 = bo[n + 1];
            float2 r0 = *(const float2*)&resid[(size_t)m * DM + n];
            float2 r1 = *(const float2*)&resid[(size_t)(m + 8) * DM + n];
            *(float2*)&outp[(size_t)m * DM + n] =
                make_float2(cv[mi][ni][0] + b0 + r0.x, cv[mi][ni][1] + b1 + r0.y);
            *(float2*)&outp[(size_t)(m + 8) * DM + n] =
                make_float2(cv[mi][ni][2] + b0 + r1.x, cv[mi][ni][3] + b1 + r1.y);
        }
    }
}

// ---------------------------------------------------------------------------
// K2: fused attention, two-sweep, precomputed mask bits.
// ---------------------------------------------------------------------------
__global__ __launch_bounds__(512, 1)
void fused_attn_kernel(const float* __restrict__ Qh,
                       const float* __restrict__ Kh,
                       const float* __restrict__ Vh,
                       const uint32_t* __restrict__ mb,
                       float* __restrict__ attn,
                       float* __restrict__ ctx) {
    extern __shared__ float sm[];
    float* Ps = sm + PS_OFF;
    float* rowsum_s = sm + RS_OFF;
    float* inv_s    = sm + INV_OFF;

    const int i0 = blockIdx.x * 128;
    const int hb = blockIdx.y;
    const int bb = hb & (B - 1);
    const int tid = threadIdx.x;
    const int wid = tid >> 5, lane = tid & 31;
    const int g = lane >> 2, tp = lane & 3;
    const int wm0  = (wid >> 1) * 16;
    const int wn0  = (wid & 1) * 64;
    const int wn0p = (wid & 1) * 32;

    const float* Qb = Qh + (size_t)hb * L * DK;
    const float* Kb = Kh + (size_t)hb * L * DK;
    const float* Vb = Vh + (size_t)hb * L * DK;
    float* attnb = attn + (size_t)hb * L * L;
    // mask words for this CTA's two rows (r0, r1), 64 words per row
    const uint32_t* mrow = mb + ((size_t)bb * L + i0) * (L / 32);

    if (tid < 128) rowsum_s[tid] = 0.f;

    // ---- stage Q, extract A-fragments ----
    for (int t = tid; t < 2048; t += 512) {
        int r = t >> 4, c4 = t & 15;
        *(float4*)&Ps[r * PSTR + c4 * 4] =
            *(const float4*)&Qb[(size_t)(i0 + r) * DK + c4 * 4];
    }
    __syncthreads();
    uint32_t qf[8][4];
    {
        int r = wm0 + g;
#pragma unroll
        for (int ks = 0; ks < 8; ks++) {
            qf[ks][0] = asu(Ps[r * PSTR + ks * 8 + tp]);
            qf[ks][1] = asu(Ps[(r + 8) * PSTR + ks * 8 + tp]);
            qf[ks][2] = asu(Ps[r * PSTR + ks * 8 + tp + 4]);
            qf[ks][3] = asu(Ps[(r + 8) * PSTR + ks * 8 + tp + 4]);
        }
    }
    __syncthreads();

    auto load_k = [&](int jt, int buf) {
        const int j0 = jt * 128;
        float* Kd = sm + (buf ? KS_OFF1 : KS_OFF0);
        for (int t = tid; t < 2048; t += 512) {
            int r = t >> 4, c4 = t & 15;
            cp_async16(&Kd[r * 68 + c4 * 4], &Kb[(size_t)(j0 + r) * DK + c4 * 4]);
        }
    };
    auto load_kv = [&](int jt, int buf) {
        const int j0 = jt * 128;
        float* Kd = sm + (buf ? KS_OFF1 : KS_OFF0);
        float* Vd = sm + (buf ? VS_OFF1 : VS_OFF0);
        for (int t = tid; t < 2048; t += 512) {
            int r = t >> 4, c4 = t & 15;
            cp_async16(&Kd[r * 68 + c4 * 4], &Kb[(size_t)(j0 + r) * DK + c4 * 4]);
            cp_async16(&Vd[r * 72 + c4 * 4], &Vb[(size_t)(j0 + r) * DK + c4 * 4]);
        }
    };

    const int r0 = wm0 + g;
    const int r1 = r0 + 8;

    // ================= SWEEP 1: rowsum only =================
    load_k(0, 0);
    cp_commit();
    float rsum[2] = {0.f, 0.f};

    for (int jt = 0; jt < 16; jt++) {
        const int cur = jt & 1;
        const int j0 = jt * 128;
        cp_wait_all();
        __syncthreads();
        if (jt + 1 < 16) { load_k(jt + 1, cur ^ 1); cp_commit(); }
        else             { load_kv(0, cur ^ 1);     cp_commit(); }

        float sacc[8][4] = {};
        const float* Kt = sm + (cur ? KS_OFF1 : KS_OFF0);
#pragma unroll
        for (int ks = 0; ks < 8; ks++) {
            uint32_t bf[8][2];
#pragma unroll
            for (int ni = 0; ni < 8; ni++) {
                bf[ni][0] = asu(Kt[(wn0 + ni * 8 + g) * 68 + ks * 8 + tp]);
                bf[ni][1] = asu(Kt[(wn0 + ni * 8 + g) * 68 + ks * 8 + tp + 4]);
            }
#pragma unroll
            for (int ni = 0; ni < 8; ni++)
                mma_tf32(sacc[ni], qf[ks], bf[ni]);
        }

        {
            int jw = (j0 >> 5) + (wn0 >> 5);
            uint32_t w0a = mrow[(size_t)r0 * 64 + jw];
            uint32_t w0b = mrow[(size_t)r0 * 64 + jw + 1];
            uint32_t w1a = mrow[(size_t)r1 * 64 + jw];
            uint32_t w1b = mrow[(size_t)r1 * 64 + jw + 1];
#pragma unroll
            for (int ni = 0; ni < 8; ni++) {
                int c = wn0 + ni * 8 + tp * 2;
                uint32_t w0 = (ni < 4) ? w0a : w0b;
                uint32_t w1 = (ni < 4) ? w1a : w1b;
                int sh = c & 31;
                float e[4];
                exp4(sacc[ni], e);
                rsum[0] += (((w0 >> sh) & 1u)       ? e[0] : 0.f)
                         + (((w0 >> (sh + 1)) & 1u) ? e[1] : 0.f);
                rsum[1] += (((w1 >> sh) & 1u)       ? e[2] : 0.f)
                         + (((w1 >> (sh + 1)) & 1u) ? e[3] : 0.f);
            }
        }
    }

    // ---- rowsum reduction -> inv ----
#pragma unroll
    for (int s = 0; s < 2; s++) {
        rsum[s] += __shfl_xor_sync(0xffffffffu, rsum[s], 1);
        rsum[s] += __shfl_xor_sync(0xffffffffu, rsum[s], 2);
    }
    if (tp == 0) {
        atomicAdd(&rowsum_s[r0], rsum[0]);
        atomicAdd(&rowsum_s[r1], rsum[1]);
    }
    __syncthreads();
    if (tid < 128) inv_s[tid] = 1.0f / rowsum_s[tid];
    __syncthreads();

    const float iv0 = inv_s[r0];
    const float iv1 = inv_s[r1];

    // ================= SWEEP 2: write attn + PV =================
    float cv[4][4] = {};

    for (int jt = 0; jt < 16; jt++) {
        const int cur = jt & 1;
        const int j0 = jt * 128;
        cp_wait_all();
        __syncthreads();
        if (jt + 1 < 16) { load_kv(jt + 1, cur ^ 1); cp_commit(); }

        float sacc[8][4] = {};
        const float* Kt = sm + (cur ? KS_OFF1 : KS_OFF0);
#pragma unroll
        for (int ks = 0; ks < 8; ks++) {
            uint32_t bf[8][2];
#pragma unroll
            for (int ni = 0; ni < 8; ni++) {
                bf[ni][0] = asu(Kt[(wn0 + ni * 8 + g) * 68 + ks * 8 + tp]);
                bf[ni][1] = asu(Kt[(wn0 + ni * 8 + g) * 68 + ks * 8 + tp + 4]);
            }
#pragma unroll
            for (int ni = 0; ni < 8; ni++)
                mma_tf32(sacc[ni], qf[ks], bf[ni]);
        }

        {
            int jw = (j0 >> 5) + (wn0 >> 5);
            uint32_t w0a = mrow[(size_t)r0 * 64 + jw];
            uint32_t w0b = mrow[(size_t)r0 * 64 + jw + 1];
            uint32_t w1a = mrow[(size_t)r1 * 64 + jw];
            uint32_t w1b = mrow[(size_t)r1 * 64 + jw + 1];
            float* arow0 = attnb + (size_t)(i0 + r0) * L + j0;
            float* arow1 = attnb + (size_t)(i0 + r1) * L + j0;
#pragma unroll
            for (int ni = 0; ni < 8; ni++) {
                int c = wn0 + ni * 8 + tp * 2;
                uint32_t w0 = (ni < 4) ? w0a : w0b;
                uint32_t w1 = (ni < 4) ? w1a : w1b;
                int sh = c & 31;
                float e[4];
                exp4(sacc[ni], e);
                float p00 = (((w0 >> sh) & 1u)       ? e[0] : 0.f) * iv0;
                float p01 = (((w0 >> (sh + 1)) & 1u) ? e[1] : 0.f) * iv0;
                float p10 = (((w1 >> sh) & 1u)       ? e[2] : 0.f) * iv1;
                float p11 = (((w1 >> (sh + 1)) & 1u) ? e[3] : 0.f) * iv1;
                *(float2*)&Ps[r0 * PSTR + c] = make_float2(p00, p01);
                *(float2*)&Ps[r1 * PSTR + c] = make_float2(p10, p11);
                *(float2*)&arow0[c] = make_float2(p00, p01);
                *(float2*)&arow1[c] = make_float2(p10, p11);
            }
        }
        __syncthreads();                       // P tile complete

        const float* Vt = sm + (cur ? VS_OFF1 : VS_OFF0);
#pragma unroll
        for (int kp = 0; kp < 16; kp++) {
            uint32_t af[4], bf2[4][2];
            {
                int r = wm0 + g;
                af[0] = f2tf32(Ps[r * PSTR + kp * 8 + tp]);
                af[1] = f2tf32(Ps[(r + 8) * PSTR + kp * 8 + tp]);
                af[2] = f2tf32(Ps[r * PSTR + kp * 8 + tp + 4]);
                af[3] = f2tf32(Ps[(r + 8) * PSTR + kp * 8 + tp + 4]);
            }
#pragma unroll
            for (int ni = 0; ni < 4; ni++) {
                bf2[ni][0] = asu(Vt[(kp * 8 + tp) * 72 + wn0p + ni * 8 + g]);
                bf2[ni][1] = asu(Vt[(kp * 8 + tp + 4) * 72 + wn0p + ni * 8 + g]);
            }
#pragma unroll
            for (int ni = 0; ni < 4; ni++)
                mma_tf32(cv[ni], af, bf2[ni]);
        }
    }

    // ---- write ctx ----
    float* ctxb = ctx + (size_t)hb * L * DK;
#pragma unroll
    for (int ni = 0; ni < 4; ni++) {
        int c = wn0p + ni * 8 + tp * 2;
        *(float2*)&ctxb[(size_t)(i0 + r0) * DK + c] = make_float2(cv[ni][0], cv[ni][1]);
        *(float2*)&ctxb[(size_t)(i0 + r1) * DK + c] = make_float2(cv[ni][2], cv[ni][3]);
    }
}

// ---------------------------------------------------------------------------
extern "C" void kernel_launch(void* const* d_in, const int* in_sizes, int n_in,
                              void* d_out, int out_size) {
    const float* q    = (const float*)d_in[0];
    const float* k    = (const float*)d_in[1];
    const float* v    = (const float*)d_in[2];
    const int*   mask = (const int*)  d_in[3];
    const float* Wq   = (const float*)d_in[4];
    const float* bq   = (const float*)d_in[5];
    const float* Wk   = (const float*)d_in[6];
    const float* bk   = (const float*)d_in[7];
    const float* Wv   = (const float*)d_in[8];
    const float* bv   = (const float*)d_in[9];
    const float* Wo   = (const float*)d_in[10];
    const float* bo   = (const float*)d_in[11];
    float* outp = (float*)d_out;

    float *Qh, *Kh, *Vh, *Ctx, *WT, *AttnFB;
    uint32_t* Mb;
    cudaGetSymbolAddress((void**)&Qh,     g_Qh);
    cudaGetSymbolAddress((void**)&Kh,     g_Kh);
    cudaGetSymbolAddress((void**)&Vh,     g_Vh);
    cudaGetSymbolAddress((void**)&Ctx,    g_ctx);
    cudaGetSymbolAddress((void**)&WT,     g_WT);
    cudaGetSymbolAddress((void**)&Mb,     g_mbits);
    cudaGetSymbolAddress((void**)&AttnFB, g_attn_fallback);

    float* attn = ((long long)out_size >= OUT_ELEMS + ATTN_ELEMS)
                      ? (outp + OUT_ELEMS) : AttnFB;

    cudaFuncSetAttribute(fused_attn_kernel,
                         cudaFuncAttributeMaxDynamicSharedMemorySize, SMEM_BYTES);
    cudaFuncSetAttribute(proj_mma_kernel,
                         cudaFuncAttributeMaxDynamicSharedMemorySize, PJ_BYTES);
    cudaFuncSetAttribute(outproj_mma_kernel,
                         cudaFuncAttributeMaxDynamicSharedMemorySize, PJ_BYTES);

    const float inv_dk = 1.0f / 64.0f;     // temperature = d_k

    transpose_w_kernel<<<dim3(16, 16, 4), dim3(32, 8)>>>(Wq, Wk, Wv, Wo, WT);
    maskbits_kernel<<<(unsigned)((size_t)B * L * (L / 32) / 8), 256>>>(mask, Mb);

    proj_mma_kernel<<<dim3(DM / 64, (B * L) / 128, 3), 256, PJ_BYTES>>>(
        q, k, v, WT, bq, bk, bv, Qh, Kh, Vh, inv_dk);

    fused_attn_kernel<<<dim3(L / 128, HB), dim3(512), SMEM_BYTES>>>(
        Qh, Kh, Vh, Mb, attn, Ctx);

    outproj_mma_kernel<<<dim3(DM / 64, (B * L) / 128), 256, PJ_BYTES>>>(
        Ctx, WT + 3 * DM * DM, bo, q, outp);
}

// round 11
// speedup vs baseline: 3.2226x; 1.3220x over previous
#include <cuda_runtime.h>
#include <cuda_bf16.h>
#include <cstdint>

// ---------------------------------------------------------------------------
// MultiHeadAttention, B=2, L=2048, H=8, d=64, d_model=512
// Round 10: attention operands moved tf32 -> bf16 (m16n8k16): halves mma
//           count, halves fragment-LDS count and smem footprint.
//           Q/K stored bf16 (d-pairs adjacent), V stored bf16 TRANSPOSED
//           [hb][d][j] (smem transpose in proj epilogue), P packed bf16x2.
//           attn output remains fp32 (error budget: S err ~7e-5 abs).
// ---------------------------------------------------------------------------

namespace {
constexpr int B  = 2;
constexpr int L  = 2048;
constexpr int DK = 64;
constexpr int DM = 512;
constexpr int HB = 16;
constexpr long long OUT_ELEMS  = (long long)B * L * DM;
constexpr long long ATTN_ELEMS = (long long)HB * L * L;

// fused-kernel smem (u32-word offsets)
constexpr int PSTR2   = 68;       // P bf16x2 tile stride (64 words + pad)
constexpr int KSTR2   = 36;       // K bf16x2 stride (32 words + pad)
constexpr int VSTR2   = 68;       // V^T bf16x2 stride (64 words + pad)
constexpr int PS_OFF  = 0;        // 128 x 68  (also Q staging 128 x 36)
constexpr int KS_OFF0 = 8704;     // 128 x 36
constexpr int KS_OFF1 = 13312;
constexpr int VS_OFF0 = 17920;    // 64 x 68
constexpr int VS_OFF1 = 22272;
constexpr int RS_OFF  = 26624;    // rowsum[128] (float)
constexpr int INV_OFF = 26752;    // inv[128] (float)
constexpr int SMEM_WORDS = 26880;
constexpr int SMEM_BYTES = SMEM_WORDS * 4;     // 107520

// proj-kernel smem (float offsets): A 128x68 x2, B 64x68 x2
constexpr int PJ_AS0 = 0;
constexpr int PJ_AS1 = 8704;
constexpr int PJ_BS0 = 17408;
constexpr int PJ_BS1 = 21760;
constexpr int PJ_FLOATS = 26112;
constexpr int PJ_BYTES  = PJ_FLOATS * 4;       // 104448
// V transpose staging reuses PJ_AS0: 64 x 136 bf16 = 4352 words
constexpr int VST_STRIDE = 136;                // bf16 units
}

// Scratch (__device__ globals)
__device__ uint32_t g_Qh2[HB * L * (DK / 2)];      // bf16x2 [hb][i][d/2]
__device__ uint32_t g_Kh2[HB * L * (DK / 2)];      // bf16x2 [hb][i][d/2]
__device__ uint32_t g_Vht[HB * DK * (L / 2)];      // bf16x2 [hb][d][j/2]
__device__ float    g_ctx[HB * L * DK];
__device__ float    g_WT[4 * DM * DM];             // tf32 W^T
__device__ uint32_t g_mbits[(size_t)B * L * (L / 32)];
__device__ float    g_attn_fallback[(size_t)HB * L * L];

// ---------------------------------------------------------------------------
__device__ __forceinline__ uint32_t f2tf32(float f) {
    uint32_t u;
    asm("cvt.rna.tf32.f32 %0, %1;" : "=r"(u) : "f"(f));
    return u;
}
__device__ __forceinline__ uint32_t pack_bf16x2(float lo, float hi) {
    uint32_t r;  // first src -> high half
    asm("cvt.rn.bf16x2.f32 %0, %1, %2;" : "=r"(r) : "f"(hi), "f"(lo));
    return r;
}
__device__ __forceinline__ void mma_tf32(float* c, const uint32_t* a, const uint32_t* b) {
    asm volatile(
        "mma.sync.aligned.m16n8k8.row.col.f32.tf32.tf32.f32 "
        "{%0,%1,%2,%3},{%4,%5,%6,%7},{%8,%9},{%0,%1,%2,%3};"
        : "+f"(c[0]), "+f"(c[1]), "+f"(c[2]), "+f"(c[3])
        : "r"(a[0]), "r"(a[1]), "r"(a[2]), "r"(a[3]), "r"(b[0]), "r"(b[1]));
}
__device__ __forceinline__ void mma_bf16(float* c, const uint32_t* a, const uint32_t* b) {
    asm volatile(
        "mma.sync.aligned.m16n8k16.row.col.f32.bf16.bf16.f32 "
        "{%0,%1,%2,%3},{%4,%5,%6,%7},{%8,%9},{%0,%1,%2,%3};"
        : "+f"(c[0]), "+f"(c[1]), "+f"(c[2]), "+f"(c[3])
        : "r"(a[0]), "r"(a[1]), "r"(a[2]), "r"(a[3]), "r"(b[0]), "r"(b[1]));
}
__device__ __forceinline__ void cp_async16(void* sdst, const void* gsrc) {
    uint32_t da = (uint32_t)__cvta_generic_to_shared(sdst);
    asm volatile("cp.async.cg.shared.global [%0], [%1], 16;" :: "r"(da), "l"(gsrc));
}
__device__ __forceinline__ void cp_commit() { asm volatile("cp.async.commit_group;"); }
__device__ __forceinline__ void cp_wait_all() { asm volatile("cp.async.wait_group 0;"); }
__device__ __forceinline__ uint32_t asu(float f) { return __float_as_uint(f); }

// exp via FMA Taylor-6 (|x| < ~0.6; rare warp-uniform MUFU fallback)
__device__ __forceinline__ float exp_poly(float x) {
    float r = 1.38888894e-3f;
    r = fmaf(r, x, 8.33333377e-3f);
    r = fmaf(r, x, 4.16666679e-2f);
    r = fmaf(r, x, 1.66666672e-1f);
    r = fmaf(r, x, 0.5f);
    r = fmaf(r, x, 1.0f);
    r = fmaf(r, x, 1.0f);
    return r;
}
__device__ __forceinline__ void exp4(const float* s, float* e) {
    e[0] = exp_poly(s[0]); e[1] = exp_poly(s[1]);
    e[2] = exp_poly(s[2]); e[3] = exp_poly(s[3]);
    float mx = fmaxf(fmaxf(fabsf(s[0]), fabsf(s[1])), fmaxf(fabsf(s[2]), fabsf(s[3])));
    if (__any_sync(0xffffffffu, mx > 0.6f)) {
        e[0] = __expf(s[0]); e[1] = __expf(s[1]);
        e[2] = __expf(s[2]); e[3] = __expf(s[3]);
    }
}

// ---------------------------------------------------------------------------
// K0a: transpose + tf32-round weights: WT[n][k] = tf32(W[k][n])
// ---------------------------------------------------------------------------
__global__ void transpose_w_kernel(const float* __restrict__ W0,
                                   const float* __restrict__ W1,
                                   const float* __restrict__ W2,
                                   const float* __restrict__ W3,
                                   float* __restrict__ outT) {
    __shared__ float t[32][33];
    const float* W = (blockIdx.z == 0) ? W0 : (blockIdx.z == 1) ? W1
                   : (blockIdx.z == 2) ? W2 : W3;
    float* o = outT + (size_t)blockIdx.z * DM * DM;
    const int k0 = blockIdx.y * 32, n0 = blockIdx.x * 32;
    const int tx = threadIdx.x, ty = threadIdx.y;
#pragma unroll
    for (int i = 0; i < 32; i += 8)
        t[ty + i][tx] = W[(size_t)(k0 + ty + i) * DM + n0 + tx];
    __syncthreads();
#pragma unroll
    for (int i = 0; i < 32; i += 8)
        o[(size_t)(n0 + ty + i) * DM + k0 + tx] =
            __uint_as_float(f2tf32(t[tx][ty + i]));
}

// ---------------------------------------------------------------------------
// K0b: pack mask to bits
// ---------------------------------------------------------------------------
__global__ void maskbits_kernel(const int* __restrict__ mask,
                                uint32_t* __restrict__ out) {
    size_t w = (size_t)blockIdx.x * 8 + (threadIdx.x >> 5);
    int lane = threadIdx.x & 31;
    int m = mask[w * 32 + lane];
    unsigned bal = __ballot_sync(0xffffffffu, m != 0);
    if (lane == 0) out[w] = bal;
}

// ---------------------------------------------------------------------------
// K1: QKV projection (tf32 mma on fp32 inputs), outputs bf16.
//     z=0: Q (scaled 1/64) -> g_Qh2; z=1: K -> g_Kh2;
//     z=2: V -> g_Vht TRANSPOSED [hb][d][j] via smem staging.
// ---------------------------------------------------------------------------
__global__ __launch_bounds__(256, 2)
void proj_mma_kernel(const float* __restrict__ q, const float* __restrict__ k,
                     const float* __restrict__ v, const float* __restrict__ WT,
                     const float* __restrict__ bq, const float* __restrict__ bk,
                     const float* __restrict__ bv,
                     uint32_t* __restrict__ Qh2, uint32_t* __restrict__ Kh2,
                     uint32_t* __restrict__ Vht, float inv_dk) {
    extern __shared__ float smp[];
    const int z = blockIdx.z;
    const float* A    = (z == 0) ? q  : (z == 1) ? k  : v;
    const float* BT   = WT + (size_t)z * DM * DM;
    const float* bias = (z == 0) ? bq : (z == 1) ? bk : bv;
    const float alpha = (z == 0) ? inv_dk : 1.0f;

    const int m0 = blockIdx.y * 128;
    const int n0 = blockIdx.x * 64;
    const int tid = threadIdx.x;
    const int wid = tid >> 5, lane = tid & 31;
    const int g = lane >> 2, tp = lane & 3;
    const int wm0 = (wid >> 1) * 32;
    const int wn0 = (wid & 1) * 32;

    auto load_chunk = [&](int kc, int buf) {
        float* As = smp + (buf ? PJ_AS1 : PJ_AS0);
        float* Bs = smp + (buf ? PJ_BS1 : PJ_BS0);
        const int k0 = kc * 64;
        for (int t = tid; t < 2048; t += 256) {
            int r = t >> 4, c4 = t & 15;
            cp_async16(&As[r * 68 + c4 * 4], &A[(size_t)(m0 + r) * DM + k0 + c4 * 4]);
        }
        for (int t = tid; t < 1024; t += 256) {
            int r = t >> 4, c4 = t & 15;
            cp_async16(&Bs[r * 68 + c4 * 4], &BT[(size_t)(n0 + r) * DM + k0 + c4 * 4]);
        }
    };
    load_chunk(0, 0);
    cp_commit();

    float cv[2][4][4] = {};
    for (int kc = 0; kc < 8; kc++) {
        cp_wait_all();
        __syncthreads();
        if (kc + 1 < 8) { load_chunk(kc + 1, (kc & 1) ^ 1); cp_commit(); }
        const float* As = smp + ((kc & 1) ? PJ_AS1 : PJ_AS0);
        const float* Bs = smp + ((kc & 1) ? PJ_BS1 : PJ_BS0);
#pragma unroll
        for (int ks = 0; ks < 8; ks++) {
            uint32_t af[2][4], bf[4][2];
#pragma unroll
            for (int mi = 0; mi < 2; mi++) {
                int r = wm0 + mi * 16 + g;
                af[mi][0] = f2tf32(As[r * 68 + ks * 8 + tp]);
                af[mi][1] = f2tf32(As[(r + 8) * 68 + ks * 8 + tp]);
                af[mi][2] = f2tf32(As[r * 68 + ks * 8 + tp + 4]);
                af[mi][3] = f2tf32(As[(r + 8) * 68 + ks * 8 + tp + 4]);
            }
#pragma unroll
            for (int ni = 0; ni < 4; ni++) {
                bf[ni][0] = asu(Bs[(wn0 + ni * 8 + g) * 68 + ks * 8 + tp]);
                bf[ni][1] = asu(Bs[(wn0 + ni * 8 + g) * 68 + ks * 8 + tp + 4]);
            }
#pragma unroll
            for (int mi = 0; mi < 2; mi++)
#pragma unroll
                for (int ni = 0; ni < 4; ni++)
                    mma_tf32(cv[mi][ni], af[mi], bf[ni]);
        }
    }

    const int hB = n0 >> 6;
    const int bb = m0 >> 11, ii0 = m0 & (L - 1);

    if (z < 2) {
        // bf16x2 packed writes to [hb][i][d/2]
        uint32_t* outw = (z == 0) ? Qh2 : Kh2;
#pragma unroll
        for (int mi = 0; mi < 2; mi++) {
            int ii = ii0 + wm0 + mi * 16 + g;
            size_t rb0 = ((size_t)(hB * B + bb) * L + ii) * (DK / 2);
            size_t rb1 = rb0 + 8 * (DK / 2);
#pragma unroll
            for (int ni = 0; ni < 4; ni++) {
                int d = wn0 + ni * 8 + tp * 2;
                float b0 = bias[n0 + d], b1 = bias[n0 + d + 1];
                outw[rb0 + (d >> 1)] = pack_bf16x2((cv[mi][ni][0] + b0) * alpha,
                                                   (cv[mi][ni][1] + b1) * alpha);
                outw[rb1 + (d >> 1)] = pack_bf16x2((cv[mi][ni][2] + b0) * alpha,
                                                   (cv[mi][ni][3] + b1) * alpha);
            }
        }
    } else {
        // V: stage transposed [d][m] bf16 in smem (reuse buffer 0), then
        // coalesced row writes to g_Vht [hb][d][j].
        __syncthreads();
        __nv_bfloat16* Vst = (__nv_bfloat16*)(smp + PJ_AS0);
#pragma unroll
        for (int mi = 0; mi < 2; mi++) {
            int ml0 = wm0 + mi * 16 + g;
#pragma unroll
            for (int ni = 0; ni < 4; ni++) {
                int d = wn0 + ni * 8 + tp * 2;
                float b0 = bias[n0 + d], b1 = bias[n0 + d + 1];
                Vst[d * VST_STRIDE + ml0]       = __float2bfloat16(cv[mi][ni][0] + b0);
                Vst[(d + 1) * VST_STRIDE + ml0] = __float2bfloat16(cv[mi][ni][1] + b1);
                Vst[d * VST_STRIDE + ml0 + 8]       = __float2bfloat16(cv[mi][ni][2] + b0);
                Vst[(d + 1) * VST_STRIDE + ml0 + 8] = __float2bfloat16(cv[mi][ni][3] + b1);
            }
        }
        __syncthreads();
        // 64 rows x 128 bf16 = 64 x 16 uint4-chunks
        for (int t = tid; t < 1024; t += 256) {
            int d = t >> 4, c = t & 15;     // c: 8-bf16 chunk
            uint4 val = *(const uint4*)((const char*)Vst + d * VST_STRIDE * 2 + c * 16);
            size_t dst = ((size_t)(hB * B + bb) * DK + d) * (L / 2) + (ii0 >> 1) + c * 4;
            *(uint4*)&Vht[dst] = val;
        }
    }
}

// ---------------------------------------------------------------------------
// K3: output projection (tf32 mma), ctx fp32 gathered.
// ---------------------------------------------------------------------------
__global__ __launch_bounds__(256, 2)
void outproj_mma_kernel(const float* __restrict__ ctx,
                        const float* __restrict__ WoT,
                        const float* __restrict__ bo,
                        const float* __restrict__ resid,
                        float* __restrict__ outp) {
    extern __shared__ float smp[];
    const int m0 = blockIdx.y * 128;
    const int n0 = blockIdx.x * 64;
    const int tid = threadIdx.x;
    const int wid = tid >> 5, lane = tid & 31;
    const int g = lane >> 2, tp = lane & 3;
    const int wm0 = (wid >> 1) * 32;
    const int wn0 = (wid & 1) * 32;

    auto load_chunk = [&](int kc, int buf) {
        float* As = smp + (buf ? PJ_AS1 : PJ_AS0);
        float* Bs = smp + (buf ? PJ_BS1 : PJ_BS0);
        for (int t = tid; t < 2048; t += 256) {
            int r = t >> 4, c4 = t & 15;
            int m = m0 + r, bb = m >> 11, ii = m & (L - 1);
            size_t base = ((size_t)(kc * B + bb) * L + ii) * DK;
            cp_async16(&As[r * 68 + c4 * 4], &ctx[base + c4 * 4]);
        }
        const int k0 = kc * 64;
        for (int t = tid; t < 1024; t += 256) {
            int r = t >> 4, c4 = t & 15;
            cp_async16(&Bs[r * 68 + c4 * 4], &WoT[(size_t)(n0 + r) * DM + k0 + c4 * 4]);
        }
    };
    load_chunk(0, 0);
    cp_commit();

    float cv[2][4][4] = {};
    for (int kc = 0; kc < 8; kc++) {
        cp_wait_all();
        __syncthreads();
        if (kc + 1 < 8) { load_chunk(kc + 1, (kc & 1) ^ 1); cp_commit(); }
        const float* As = smp + ((kc & 1) ? PJ_AS1 : PJ_AS0);
        const float* Bs = smp + ((kc & 1) ? PJ_BS1 : PJ_BS0);
#pragma unroll
        for (int ks = 0; ks < 8; ks++) {
            uint32_t af[2][4], bf[4][2];
#pragma unroll
            for (int mi = 0; mi < 2; mi++) {
                int r = wm0 + mi * 16 + g;
                af[mi][0] = f2tf32(As[r * 68 + ks * 8 + tp]);
                af[mi][1] = f2tf32(As[(r + 8) * 68 + ks * 8 + tp]);
                af[mi][2] = f2tf32(As[r * 68 + ks * 8 + tp + 4]);
                af[mi][3] = f2tf32(As[(r + 8) * 68 + ks * 8 + tp + 4]);
            }
#pragma unroll
            for (int ni = 0; ni < 4; ni++) {
                bf[ni][0] = asu(Bs[(wn0 + ni * 8 + g) * 68 + ks * 8 + tp]);
                bf[ni][1] = asu(Bs[(wn0 + ni * 8 + g) * 68 + ks * 8 + tp + 4]);
            }
#pragma unroll
            for (int mi = 0; mi < 2; mi++)
#pragma unroll
                for (int ni = 0; ni < 4; ni++)
                    mma_tf32(cv[mi][ni], af[mi], bf[ni]);
        }
    }

#pragma unroll
    for (int mi = 0; mi < 2; mi++) {
        int m = m0 + wm0 + mi * 16 + g;
#pragma unroll
        for (int ni = 0; ni < 4; ni++) {
            int n = n0 + wn0 + ni * 8 + tp * 2;
            float b0 = bo[n], b1 = bo[n + 1];
            float2 r0 = *(const float2*)&resid[(size_t)m * DM + n];
            float2 r1 = *(const float2*)&resid[(size_t)(m + 8) * DM + n];
            *(float2*)&outp[(size_t)m * DM + n] =
                make_float2(cv[mi][ni][0] + b0 + r0.x, cv[mi][ni][1] + b1 + r0.y);
            *(float2*)&outp[(size_t)(m + 8) * DM + n] =
                make_float2(cv[mi][ni][2] + b0 + r1.x, cv[mi][ni][3] + b1 + r1.y);
        }
    }
}

// ---------------------------------------------------------------------------
// K2: fused attention, bf16 operands, two-sweep, precomputed mask bits.
// ---------------------------------------------------------------------------
__global__ __launch_bounds__(512, 1)
void fused_attn_kernel(const uint32_t* __restrict__ Qh2,
                       const uint32_t* __restrict__ Kh2,
                       const uint32_t* __restrict__ Vht,
                       const uint32_t* __restrict__ mb,
                       float* __restrict__ attn,
                       float* __restrict__ ctx) {
    extern __shared__ uint32_t smw[];
    uint32_t* Ps2 = smw + PS_OFF;             // P bf16x2, 128 x PSTR2
    float* rowsum_s = (float*)(smw + RS_OFF);
    float* inv_s    = (float*)(smw + INV_OFF);

    const int i0 = blockIdx.x * 128;
    const int hb = blockIdx.y;
    const int bb = hb & (B - 1);
    const int tid = threadIdx.x;
    const int wid = tid >> 5, lane = tid & 31;
    const int g = lane >> 2, tp = lane & 3;
    const int wm0  = (wid >> 1) * 16;
    const int wn0  = (wid & 1) * 64;
    const int wn0p = (wid & 1) * 32;

    const uint32_t* Qb2 = Qh2 + (size_t)hb * L * (DK / 2);
    const uint32_t* Kb2 = Kh2 + (size_t)hb * L * (DK / 2);
    const uint32_t* Vb2 = Vht + (size_t)hb * DK * (L / 2);
    float* attnb = attn + (size_t)hb * L * L;
    const uint32_t* mrow = mb + ((size_t)bb * L + i0) * (L / 32);

    if (tid < 128) rowsum_s[tid] = 0.f;

    // ---- stage Q (bf16x2 rows: 32 words each), extract A-fragments ----
    for (int t = tid; t < 1024; t += 512) {   // 128 rows x 8 uint4-chunks
        int r = t >> 3, c4 = t & 7;
        *(uint4*)&Ps2[r * KSTR2 + c4 * 4] =
            *(const uint4*)&Qb2[(size_t)(i0 + r) * (DK / 2) + c4 * 4];
    }
    __syncthreads();
    uint32_t qf[4][4];
    {
        int r = wm0 + g;
#pragma unroll
        for (int ks = 0; ks < 4; ks++) {
            qf[ks][0] = Ps2[r * KSTR2 + ks * 8 + tp];
            qf[ks][1] = Ps2[(r + 8) * KSTR2 + ks * 8 + tp];
            qf[ks][2] = Ps2[r * KSTR2 + ks * 8 + tp + 4];
            qf[ks][3] = Ps2[(r + 8) * KSTR2 + ks * 8 + tp + 4];
        }
    }
    __syncthreads();

    auto load_k = [&](int jt, int buf) {
        const int j0 = jt * 128;
        uint32_t* Kd = smw + (buf ? KS_OFF1 : KS_OFF0);
        for (int t = tid; t < 1024; t += 512) {    // 128 rows x 8 chunks
            int r = t >> 3, c4 = t & 7;
            cp_async16(&Kd[r * KSTR2 + c4 * 4],
                       &Kb2[(size_t)(j0 + r) * (DK / 2) + c4 * 4]);
        }
    };
    auto load_kv = [&](int jt, int buf) {
        const int j0 = jt * 128;
        uint32_t* Kd = smw + (buf ? KS_OFF1 : KS_OFF0);
        uint32_t* Vd = smw + (buf ? VS_OFF1 : VS_OFF0);
        for (int t = tid; t < 1024; t += 512) {
            int r = t >> 3, c4 = t & 7;
            cp_async16(&Kd[r * KSTR2 + c4 * 4],
                       &Kb2[(size_t)(j0 + r) * (DK / 2) + c4 * 4]);
        }
        for (int t = tid; t < 1024; t += 512) {    // 64 d-rows x 16 chunks
            int d = t >> 4, c4 = t & 15;
            cp_async16(&Vd[d * VSTR2 + c4 * 4],
                       &Vb2[(size_t)d * (L / 2) + (j0 >> 1) + c4 * 4]);
        }
    };

    const int r0 = wm0 + g;
    const int r1 = r0 + 8;

    // ================= SWEEP 1: rowsum only =================
    load_k(0, 0);
    cp_commit();
    float rsum[2] = {0.f, 0.f};

    for (int jt = 0; jt < 16; jt++) {
        const int cur = jt & 1;
        const int j0 = jt * 128;
        cp_wait_all();
        __syncthreads();
        if (jt + 1 < 16) { load_k(jt + 1, cur ^ 1); cp_commit(); }
        else             { load_kv(0, cur ^ 1);     cp_commit(); }

        float sacc[8][4] = {};
        const uint32_t* Kt = smw + (cur ? KS_OFF1 : KS_OFF0);
#pragma unroll
        for (int ks = 0; ks < 4; ks++) {
            uint32_t bf[8][2];
#pragma unroll
            for (int ni = 0; ni < 8; ni++) {
                bf[ni][0] = Kt[(wn0 + ni * 8 + g) * KSTR2 + ks * 8 + tp];
                bf[ni][1] = Kt[(wn0 + ni * 8 + g) * KSTR2 + ks * 8 + tp + 4];
            }
#pragma unroll
            for (int ni = 0; ni < 8; ni++)
                mma_bf16(sacc[ni], qf[ks], bf[ni]);
        }

        {
            int jw = (j0 >> 5) + (wn0 >> 5);
            uint32_t w0a = mrow[(size_t)r0 * 64 + jw];
            uint32_t w0b = mrow[(size_t)r0 * 64 + jw + 1];
            uint32_t w1a = mrow[(size_t)r1 * 64 + jw];
            uint32_t w1b = mrow[(size_t)r1 * 64 + jw + 1];
#pragma unroll
            for (int ni = 0; ni < 8; ni++) {
                int c = wn0 + ni * 8 + tp * 2;
                uint32_t w0 = (ni < 4) ? w0a : w0b;
                uint32_t w1 = (ni < 4) ? w1a : w1b;
                int sh = c & 31;
                float e[4];
                exp4(sacc[ni], e);
                rsum[0] += (((w0 >> sh) & 1u)       ? e[0] : 0.f)
                         + (((w0 >> (sh + 1)) & 1u) ? e[1] : 0.f);
                rsum[1] += (((w1 >> sh) & 1u)       ? e[2] : 0.f)
                         + (((w1 >> (sh + 1)) & 1u) ? e[3] : 0.f);
            }
        }
    }

#pragma unroll
    for (int s = 0; s < 2; s++) {
        rsum[s] += __shfl_xor_sync(0xffffffffu, rsum[s], 1);
        rsum[s] += __shfl_xor_sync(0xffffffffu, rsum[s], 2);
    }
    if (tp == 0) {
        atomicAdd(&rowsum_s[r0], rsum[0]);
        atomicAdd(&rowsum_s[r1], rsum[1]);
    }
    __syncthreads();
    if (tid < 128) inv_s[tid] = 1.0f / rowsum_s[tid];
    __syncthreads();

    const float iv0 = inv_s[r0];
    const float iv1 = inv_s[r1];

    // ================= SWEEP 2: write attn + PV =================
    float cv[4][4] = {};

    for (int jt = 0; jt < 16; jt++) {
        const int cur = jt & 1;
        const int j0 = jt * 128;
        cp_wait_all();
        __syncthreads();
        if (jt + 1 < 16) { load_kv(jt + 1, cur ^ 1); cp_commit(); }

        float sacc[8][4] = {};
        const uint32_t* Kt = smw + (cur ? KS_OFF1 : KS_OFF0);
#pragma unroll
        for (int ks = 0; ks < 4; ks++) {
            uint32_t bf[8][2];
#pragma unroll
            for (int ni = 0; ni < 8; ni++) {
                bf[ni][0] = Kt[(wn0 + ni * 8 + g) * KSTR2 + ks * 8 + tp];
                bf[ni][1] = Kt[(wn0 + ni * 8 + g) * KSTR2 + ks * 8 + tp + 4];
            }
#pragma unroll
            for (int ni = 0; ni < 8; ni++)
                mma_bf16(sacc[ni], qf[ks], bf[ni]);
        }

        {
            int jw = (j0 >> 5) + (wn0 >> 5);
            uint32_t w0a = mrow[(size_t)r0 * 64 + jw];
            uint32_t w0b = mrow[(size_t)r0 * 64 + jw + 1];
            uint32_t w1a = mrow[(size_t)r1 * 64 + jw];
            uint32_t w1b = mrow[(size_t)r1 * 64 + jw + 1];
            float* arow0 = attnb + (size_t)(i0 + r0) * L + j0;
            float* arow1 = attnb + (size_t)(i0 + r1) * L + j0;
#pragma unroll
            for (int ni = 0; ni < 8; ni++) {
                int c = wn0 + ni * 8 + tp * 2;
                uint32_t w0 = (ni < 4) ? w0a : w0b;
                uint32_t w1 = (ni < 4) ? w1a : w1b;
                int sh = c & 31;
                float e[4];
                exp4(sacc[ni], e);
                float p00 = (((w0 >> sh) & 1u)       ? e[0] : 0.f) * iv0;
                float p01 = (((w0 >> (sh + 1)) & 1u) ? e[1] : 0.f) * iv0;
                float p10 = (((w1 >> sh) & 1u)       ? e[2] : 0.f) * iv1;
                float p11 = (((w1 >> (sh + 1)) & 1u) ? e[3] : 0.f) * iv1;
                Ps2[r0 * PSTR2 + (c >> 1)] = pack_bf16x2(p00, p01);
                Ps2[r1 * PSTR2 + (c >> 1)] = pack_bf16x2(p10, p11);
                *(float2*)&arow0[c] = make_float2(p00, p01);
                *(float2*)&arow1[c] = make_float2(p10, p11);
            }
        }
        __syncthreads();                       // P tile complete

        const uint32_t* Vt = smw + (cur ? VS_OFF1 : VS_OFF0);
#pragma unroll
        for (int kp = 0; kp < 8; kp++) {
            uint32_t af[4], bf2[4][2];
            af[0] = Ps2[r0 * PSTR2 + kp * 8 + tp];
            af[1] = Ps2[r1 * PSTR2 + kp * 8 + tp];
            af[2] = Ps2[r0 * PSTR2 + kp * 8 + tp + 4];
            af[3] = Ps2[r1 * PSTR2 + kp * 8 + tp + 4];
#pragma unroll
            for (int ni = 0; ni < 4; ni++) {
                bf2[ni][0] = Vt[(wn0p + ni * 8 + g) * VSTR2 + kp * 8 + tp];
                bf2[ni][1] = Vt[(wn0p + ni * 8 + g) * VSTR2 + kp * 8 + tp + 4];
            }
#pragma unroll
            for (int ni = 0; ni < 4; ni++)
                mma_bf16(cv[ni], af, bf2[ni]);
        }
    }

    // ---- write ctx ----
    float* ctxb = ctx + (size_t)hb * L * DK;
#pragma unroll
    for (int ni = 0; ni < 4; ni++) {
        int c = wn0p + ni * 8 + tp * 2;
        *(float2*)&ctxb[(size_t)(i0 + r0) * DK + c] = make_float2(cv[ni][0], cv[ni][1]);
        *(float2*)&ctxb[(size_t)(i0 + r1) * DK + c] = make_float2(cv[ni][2], cv[ni][3]);
    }
}

// ---------------------------------------------------------------------------
extern "C" void kernel_launch(void* const* d_in, const int* in_sizes, int n_in,
                              void* d_out, int out_size) {
    const float* q    = (const float*)d_in[0];
    const float* k    = (const float*)d_in[1];
    const float* v    = (const float*)d_in[2];
    const int*   mask = (const int*)  d_in[3];
    const float* Wq   = (const float*)d_in[4];
    const float* bq   = (const float*)d_in[5];
    const float* Wk   = (const float*)d_in[6];
    const float* bk   = (const float*)d_in[7];
    const float* Wv   = (const float*)d_in[8];
    const float* bv   = (const float*)d_in[9];
    const float* Wo   = (const float*)d_in[10];
    const float* bo   = (const float*)d_in[11];
    float* outp = (float*)d_out;

    float *Ctx, *WT, *AttnFB;
    uint32_t *Qh2, *Kh2, *Vht, *Mb;
    cudaGetSymbolAddress((void**)&Qh2,    g_Qh2);
    cudaGetSymbolAddress((void**)&Kh2,    g_Kh2);
    cudaGetSymbolAddress((void**)&Vht,    g_Vht);
    cudaGetSymbolAddress((void**)&Ctx,    g_ctx);
    cudaGetSymbolAddress((void**)&WT,     g_WT);
    cudaGetSymbolAddress((void**)&Mb,     g_mbits);
    cudaGetSymbolAddress((void**)&AttnFB, g_attn_fallback);

    float* attn = ((long long)out_size >= OUT_ELEMS + ATTN_ELEMS)
                      ? (outp + OUT_ELEMS) : AttnFB;

    cudaFuncSetAttribute(fused_attn_kernel,
                         cudaFuncAttributeMaxDynamicSharedMemorySize, SMEM_BYTES);
    cudaFuncSetAttribute(proj_mma_kernel,
                         cudaFuncAttributeMaxDynamicSharedMemorySize, PJ_BYTES);
    cudaFuncSetAttribute(outproj_mma_kernel,
                         cudaFuncAttributeMaxDynamicSharedMemorySize, PJ_BYTES);

    const float inv_dk = 1.0f / 64.0f;

    transpose_w_kernel<<<dim3(16, 16, 4), dim3(32, 8)>>>(Wq, Wk, Wv, Wo, WT);
    maskbits_kernel<<<(unsigned)((size_t)B * L * (L / 32) / 8), 256>>>(mask, Mb);

    proj_mma_kernel<<<dim3(DM / 64, (B * L) / 128, 3), 256, PJ_BYTES>>>(
        q, k, v, WT, bq, bk, bv, Qh2, Kh2, Vht, inv_dk);

    fused_attn_kernel<<<dim3(L / 128, HB), dim3(512), SMEM_BYTES>>>(
        Qh2, Kh2, Vht, Mb, attn, Ctx);

    outproj_mma_kernel<<<dim3(DM / 64, (B * L) / 128), 256, PJ_BYTES>>>(
        Ctx, WT + 3 * DM * DM, bo, q, outp);
}